// round 4
// baseline (speedup 1.0000x reference)
#include <cuda_runtime.h>
#include <math.h>

#define NN 32768
#define EE 524288
#define CC 16
#define MIDD 32
#define HH 8
#define Y0F 0.28209479177387814f
#define CUTOFFF 4.6f
#define KCOULF 0.529f

typedef unsigned long long ull;

// ---------------- device scratch ----------------
__device__ __align__(16) float g_x[NN * CC];
__device__ __align__(16) float g_S[NN * CC];
__device__ __align__(16) float g_q[NN * HH];
__device__ __align__(16) float g_u[NN * MIDD];
__device__ __align__(16) float g_P[NN * 512];    // [n][mq(8)][j(8)][r(4)? pair-interleaved: mq*64 + j*8 + r*2 + t], t=0:o=j, t=1:o=j+8
__device__ __align__(16) float g_PB[NN * CC];    // pair-interleaved: n*16 + j*2 + t
__device__ __align__(16) float g_feats[NN * CC];
__device__ __align__(16) float g_vl[EE * CC];    // dst-sorted: [pd][j][2] = {val, logit}
__device__ __align__(16) float g_msgD[EE * CC];  // dst-sorted
__device__ float g_distS[EE];
__device__ float g_scaleS[EE];
__device__ float g_scaleD[EE];
__device__ float g_contribD[EE];
__device__ int g_srcS[EE];
__device__ int g_dstS[EE];
__device__ int g_posd[EE];
__device__ int g_csrc[NN], g_cdst[NN];
__device__ int g_rdst[NN + 1];
__device__ int g_cursrc[NN], g_curdst[NN];
__device__ int g_rsrc_unused[NN + 1];

// ---------------- f32x2 helpers ----------------
__device__ __forceinline__ ull pack2(float a, float b) {
    ull r;
    asm("mov.b64 %0, {%1, %2};" : "=l"(r) : "f"(a), "f"(b));
    return r;
}
__device__ __forceinline__ ull fma2(ull a, ull b, ull c) {
    ull d;
    asm("fma.rn.f32x2 %0, %1, %2, %3;" : "=l"(d) : "l"(a), "l"(b), "l"(c));
    return d;
}
__device__ __forceinline__ void unpack2(ull v, float& lo, float& hi) {
    asm("mov.b64 {%0, %1}, %2;" : "=f"(lo), "=f"(hi) : "l"(v));
}

// ---------------- init ----------------
__global__ void k_init_nodes(const int* __restrict__ species,
                             const float* __restrict__ emb,
                             float* __restrict__ out) {
    int n = blockIdx.x * blockDim.x + threadIdx.x;
    if (n >= NN) return;
    int sp = species[n] - 1;
#pragma unroll
    for (int c = 0; c < CC; c++) {
        g_x[n * CC + c] = emb[sp * CC + c];
        g_S[n * CC + c] = 0.f;
    }
    g_csrc[n] = 0;
    g_cdst[n] = 0;
    if (n == 0) out[0] = 0.f;
}

__global__ void k_hist(const int* __restrict__ src, const int* __restrict__ dst) {
    int e = blockIdx.x * 256 + threadIdx.x;
    atomicAdd(&g_csrc[src[e]], 1);
    atomicAdd(&g_cdst[dst[e]], 1);
}

__global__ void k_scan() {
    const int T = 1024, PER = NN / 1024;
    __shared__ int part[T];
    int* cnt = blockIdx.x == 0 ? g_csrc : g_cdst;
    int* row = blockIdx.x == 0 ? g_rsrc_unused : g_rdst;
    int* cur = blockIdx.x == 0 ? g_cursrc : g_curdst;
    int t = threadIdx.x;
    int base = t * PER;
    int loc[PER];
    int s = 0;
#pragma unroll
    for (int i = 0; i < PER; i++) { loc[i] = cnt[base + i]; s += loc[i]; }
    part[t] = s;
    __syncthreads();
    for (int off = 1; off < T; off <<= 1) {
        int v = (t >= off) ? part[t - off] : 0;
        __syncthreads();
        part[t] += v;
        __syncthreads();
    }
    int run = part[t] - s;
#pragma unroll
    for (int i = 0; i < PER; i++) {
        row[base + i] = run;
        cur[base + i] = run;
        run += loc[i];
    }
    if (t == T - 1) row[NN] = run;
}

__global__ void k_scatter(const int* __restrict__ src, const int* __restrict__ dst,
                          const float* __restrict__ rel_pos,
                          const int* __restrict__ species) {
    int e = blockIdx.x * 256 + threadIdx.x;
    int s = src[e], d = dst[e];
    float px = rel_pos[e * 3 + 0], py = rel_pos[e * 3 + 1], pz = rel_pos[e * 3 + 2];
    float dist = sqrtf(px * px + py * py + pz * pz);
    float xc = dist / CUTOFFF;
    bool in_cut = dist < CUTOFFF;
    float x2 = in_cut ? fminf(xc * xc, 1.f - 1e-6f) : 0.f;
    float scale = in_cut ? expf(3.f - 3.f / (1.f - x2)) : 0.f;

    int ps = atomicAdd(&g_cursrc[s], 1);
    int pd = atomicAdd(&g_curdst[d], 1);
    g_srcS[ps] = s;
    g_dstS[ps] = d;
    g_posd[ps] = pd;
    g_distS[ps] = dist;
    g_scaleS[ps] = scale;
    g_scaleD[pd] = scale;

    float Zu = (float)species[s];
    float Zv = (float)species[d];
    float raw = KCOULF * Zu * Zv / (2.f * dist);
    float au = 0.8854f * 0.529f / (__powf(Zu, 0.23f) + __powf(Zv, 0.23f));
    float xx = dist / au;
    float screen = 0.1818f * __expf(-3.2f * xx) + 0.5099f * __expf(-0.9423f * xx)
                 + 0.2802f * __expf(-0.4028f * xx) + 0.02817f * __expf(-0.2016f * xx);
    g_contribD[pd] = raw * screen * scale;
}

// ---------------- fused node kernel ----------------
// mode 0: initial prep (x=emb, S=0); mode 1: attn+proj+prep next kv; mode 2: attn+proj+prep fin+Wself
// 256 threads = 32 nodes x 8 lanes
#define W3P_STRIDE 1036
__global__ void __launch_bounds__(256)
k_node_layer(int mode,
             const float* __restrict__ Wproj,
             const float* __restrict__ Wq,
             const float* __restrict__ W3,
             const float* __restrict__ b3,
             const float* __restrict__ W1n,
             const float* __restrict__ b1n,
             const float* __restrict__ Wself) {
    __shared__ float sW3p[8 * W3P_STRIDE];   // pair-interleaved: [j][i][m][t] at j*1036 + i*64 + m*2 + t
    __shared__ float sW1[CC * MIDD];
    __shared__ float sWq[HH * CC];
    __shared__ float sWproj[CC * 24];
    __shared__ float sb3[256];
    __shared__ float sb1[MIDD];
    __shared__ float sWself[CC * CC];
    __shared__ float sAgg[32 * HH];
    __shared__ float sXold[32 * CC];
    __shared__ float sXn[32 * CC];
    __shared__ float sSn[32 * CC];

    int tid = threadIdx.x;
    int nloc = tid >> 3, j = tid & 7;
    int n = blockIdx.x * 32 + nloc;

    for (int idx = tid; idx < MIDD * 256; idx += 256) {
        int m = idx >> 8, k = idx & 255;
        int o = k >> 4, i = k & 15;
        sW3p[(o & 7) * W3P_STRIDE + i * 64 + m * 2 + (o >> 3)] = W3[idx];
    }
    for (int idx = tid; idx < CC * MIDD; idx += 256) sW1[idx] = W1n[idx];
    if (tid < HH * CC && mode != 2) sWq[tid] = Wq[tid];
    if (mode != 0) for (int idx = tid; idx < CC * 24; idx += 256) sWproj[idx] = Wproj[idx];
    sb3[tid] = b3[tid];
    if (tid < MIDD) sb1[tid] = b1n[tid];
    if (tid < CC * CC && mode == 2) sWself[tid] = Wself[tid];

    if (mode != 0) {
        int beg = g_rdst[n], end = g_rdst[n + 1];
        float mx = -INFINITY;
        for (int i = beg; i < end; i++) {
            float2 vl = *(const float2*)(g_vl + (size_t)i * CC + j * 2);
            mx = fmaxf(mx, vl.y);
        }
        float num = 0.f, den = 0.f;
        for (int i = beg; i < end; i++) {
            float2 vl = *(const float2*)(g_vl + (size_t)i * CC + j * 2);
            float w = g_scaleD[i] * __expf(vl.y - mx);
            den += w;
            num = fmaf(w, vl.x, num);
        }
        sAgg[nloc * HH + j] = num / fmaxf(den, 1e-20f);
        sXold[nloc * CC + j] = g_x[n * CC + j];
        sXold[nloc * CC + 8 + j] = g_x[n * CC + 8 + j];
        __syncthreads();
        float xn0 = 0.f, xn1 = 0.f;
#pragma unroll
        for (int k = 0; k < 8; k++) {
            float a = sAgg[nloc * HH + k];
            xn0 = fmaf(sWproj[j * 24 + k], a, xn0);
            xn1 = fmaf(sWproj[(j + 8) * 24 + k], a, xn1);
        }
#pragma unroll
        for (int k = 0; k < CC; k++) {
            float xo = sXold[nloc * CC + k];
            xn0 = fmaf(sWproj[j * 24 + 8 + k], xo, xn0);
            xn1 = fmaf(sWproj[(j + 8) * 24 + 8 + k], xo, xn1);
        }
        float s0 = g_S[n * CC + j] + xn0;
        float s1 = g_S[n * CC + 8 + j] + xn1;
        g_x[n * CC + j] = xn0;     g_x[n * CC + 8 + j] = xn1;
        g_S[n * CC + j] = s0;      g_S[n * CC + 8 + j] = s1;
        sXn[nloc * CC + j] = xn0;  sXn[nloc * CC + 8 + j] = xn1;
        sSn[nloc * CC + j] = s0;   sSn[nloc * CC + 8 + j] = s1;
        __syncthreads();
    } else {
        sXn[nloc * CC + j] = g_x[n * CC + j];
        sXn[nloc * CC + 8 + j] = g_x[n * CC + 8 + j];
        sSn[nloc * CC + j] = 0.f;
        sSn[nloc * CC + 8 + j] = 0.f;
        __syncthreads();
    }

    if (mode != 2) {
        float qa = 0.f;
#pragma unroll
        for (int c = 0; c < CC; c++) qa = fmaf(sWq[j * CC + c], sXn[nloc * CC + c], qa);
        g_q[n * HH + j] = qa;
    }
    {
        float u0 = sb1[j], u1 = sb1[j + 8], u2 = sb1[j + 16], u3 = sb1[j + 24];
#pragma unroll
        for (int c = 0; c < CC; c++) {
            float sv = sSn[nloc * CC + c];
            u0 = fmaf(sv, sW1[c * MIDD + j], u0);
            u1 = fmaf(sv, sW1[c * MIDD + j + 8], u1);
            u2 = fmaf(sv, sW1[c * MIDD + j + 16], u2);
            u3 = fmaf(sv, sW1[c * MIDD + j + 24], u3);
        }
        g_u[n * MIDD + j] = u0;
        g_u[n * MIDD + j + 8] = u1;
        g_u[n * MIDD + j + 16] = u2;
        g_u[n * MIDD + j + 24] = u3;
    }
    {
        float pb0 = 0.f, pb1 = 0.f;
#pragma unroll
        for (int i = 0; i < CC; i++) {
            float xv = sXn[nloc * CC + i];
            pb0 = fmaf(sb3[j * CC + i], xv, pb0);
            pb1 = fmaf(sb3[(j + 8) * CC + i], xv, pb1);
        }
        g_PB[n * CC + j * 2] = pb0;       // pair-interleaved
        g_PB[n * CC + j * 2 + 1] = pb1;
    }
    if (mode == 2) {
        float f0 = 0.f, f1 = 0.f;
#pragma unroll
        for (int i = 0; i < CC; i++) {
            float xv = sXn[nloc * CC + i];
            f0 = fmaf(sWself[j * CC + i], xv, f0);
            f1 = fmaf(sWself[(j + 8) * CC + i], xv, f1);
        }
        g_feats[n * CC + j] = f0;
        g_feats[n * CC + 8 + j] = f1;
    }
    // P: lane j owns o-pair (j, j+8); acc[mq][r] = f32x2 pair at m = mq*4+r
    {
        ull acc[8][4];
#pragma unroll
        for (int mq = 0; mq < 8; mq++)
#pragma unroll
            for (int r = 0; r < 4; r++) acc[mq][r] = 0ULL;
#pragma unroll
        for (int i = 0; i < CC; i++) {
            float xv = sXn[nloc * CC + i];
            ull xx = pack2(xv, xv);
            const ull* wp = (const ull*)&sW3p[j * W3P_STRIDE + i * 64];
#pragma unroll
            for (int mq = 0; mq < 8; mq++) {
                acc[mq][0] = fma2(xx, wp[mq * 4 + 0], acc[mq][0]);
                acc[mq][1] = fma2(xx, wp[mq * 4 + 1], acc[mq][1]);
                acc[mq][2] = fma2(xx, wp[mq * 4 + 2], acc[mq][2]);
                acc[mq][3] = fma2(xx, wp[mq * 4 + 3], acc[mq][3]);
            }
        }
        float* Pn = g_P + (size_t)n * 512;
#pragma unroll
        for (int mq = 0; mq < 8; mq++) {
            *(ulonglong2*)(Pn + mq * 64 + j * 8)     = make_ulonglong2(acc[mq][0], acc[mq][1]);
            *(ulonglong2*)(Pn + mq * 64 + j * 8 + 4) = make_ulonglong2(acc[mq][2], acc[mq][3]);
        }
    }
}

// ---------------- edge kernel: u-trick radial + packed W2 + smem h2 + f32x2 phase B ----------------
template <bool FIN>
__global__ void __launch_bounds__(128)
k_edge(const float* __restrict__ W1, const float* __restrict__ W2,
       const float* __restrict__ b2) {
    __shared__ __align__(16) float sW2[MIDD * MIDD];
    __shared__ __align__(16) float sB2[MIDD];
    __shared__ float sw15[MIDD];
    __shared__ __align__(16) float sh_h2[128 * 36];
    __shared__ int sh_s[128];
    __shared__ float sh_bs[128];
    __shared__ int sh_pd[128];
    __shared__ int sh_d[128];
    int tid = threadIdx.x;
    for (int i = tid; i < MIDD * MIDD; i += 128) sW2[i] = W2[i];
    if (tid < MIDD) { sB2[tid] = b2[tid]; sw15[tid] = W1[15 * MIDD + tid]; }
    __syncthreads();

    // ---- phase A: one thread per edge ----
    int e = blockIdx.x * 128 + tid;
    int s = g_srcS[e];
    float dist = g_distS[e];
    {
        float h1[MIDD];
        const float4* up = (const float4*)(g_u + (size_t)s * MIDD);
#pragma unroll
        for (int t = 0; t < 8; t++) {
            float4 uv = up[t];
            h1[4 * t + 0] = fmaxf(fmaf(dist, sw15[4 * t + 0], uv.x), 0.f);
            h1[4 * t + 1] = fmaxf(fmaf(dist, sw15[4 * t + 1], uv.y), 0.f);
            h1[4 * t + 2] = fmaxf(fmaf(dist, sw15[4 * t + 2], uv.z), 0.f);
            h1[4 * t + 3] = fmaxf(fmaf(dist, sw15[4 * t + 3], uv.w), 0.f);
        }
        ull acc[16];
#pragma unroll
        for (int jp = 0; jp < 16; jp++)
            acc[jp] = *(const ull*)&sB2[2 * jp];
#pragma unroll
        for (int i2 = 0; i2 < MIDD; i2++) {
            ull xx = pack2(h1[i2], h1[i2]);
#pragma unroll
            for (int jp = 0; jp < 16; jp++) {
                ull w = *(const ull*)&sW2[i2 * MIDD + 2 * jp];
                acc[jp] = fma2(xx, w, acc[jp]);
            }
        }
#pragma unroll
        for (int jp = 0; jp < 16; jp++) {
            float lo, hi;
            unpack2(acc[jp], lo, hi);
            sh_h2[tid * 36 + 2 * jp] = fmaxf(lo, 0.f);
            sh_h2[tid * 36 + 2 * jp + 1] = fmaxf(hi, 0.f);
        }
    }
    sh_s[tid] = s;
    sh_bs[tid] = Y0F * g_scaleS[e];
    sh_pd[tid] = g_posd[e];
    if (!FIN) sh_d[tid] = g_dstS[e];
    __syncthreads();

    // ---- phase B: 8 lanes per edge, f32x2 contraction over pair-interleaved P ----
    int j = tid & 7;
    int g = tid >> 3;
#pragma unroll 1
    for (int sub = 0; sub < 8; sub++) {
        int eloc = sub * 16 + g;
        int es = sh_s[eloc];
        int epd = sh_pd[eloc];
        float ebs = sh_bs[eloc];
        const float* Pn = g_P + (size_t)es * 512;
        ull acc = *(const ull*)(g_PB + es * CC + j * 2);
#pragma unroll
        for (int mq = 0; mq < 8; mq++) {
            const ull* pp = (const ull*)(Pn + mq * 64 + j * 8);
            float4 h = *(const float4*)&sh_h2[eloc * 36 + mq * 4];
            acc = fma2(pack2(h.x, h.x), pp[0], acc);
            acc = fma2(pack2(h.y, h.y), pp[1], acc);
            acc = fma2(pack2(h.z, h.z), pp[2], acc);
            acc = fma2(pack2(h.w, h.w), pp[3], acc);
        }
        float v0, v1;
        unpack2(acc, v0, v1);
        v0 *= ebs;
        v1 *= ebs;
        if (!FIN) {
            int ed = sh_d[eloc];
            float lg = v1 * g_q[ed * HH + j];
            *(float2*)(g_vl + (size_t)epd * CC + j * 2) = make_float2(v0, lg);
        } else {
            g_msgD[(size_t)epd * CC + j] = v0;
            g_msgD[(size_t)epd * CC + 8 + j] = v1;
        }
    }
}

// ---------------- final: gather msg + coulomb + per-atom MLP + reduce ----------------
__device__ __forceinline__ float siluf(float x) { return x / (1.f + __expf(-x)); }

__global__ void k_final(const int* __restrict__ species, const float* __restrict__ emb,
                        const float* __restrict__ W1, const float* __restrict__ b1,
                        const float* __restrict__ W2, const float* __restrict__ b2,
                        const float* __restrict__ W3, const float* __restrict__ b3,
                        float* __restrict__ out) {
    __shared__ float sFeat[16 * 17];
    __shared__ float sEmb[16 * 17];
    __shared__ float sH[16 * 17];
    __shared__ float sCoul[16];
    __shared__ float sRed[16];
    int tid = threadIdx.x;
    int nloc = tid >> 4, o = tid & 15;
    int n = blockIdx.x * 16 + nloc;
    int beg = g_rdst[n], end = g_rdst[n + 1];
    float f = g_feats[n * CC + o];
    for (int i = beg; i < end; i++) f += g_msgD[(size_t)i * CC + o];
    sFeat[nloc * 17 + o] = f;
    if (o == 0) {
        float c = 0.f;
        for (int i = beg; i < end; i++) c += g_contribD[i];
        sCoul[nloc] = c;
    }
    int sp = species[n] - 1;
    sEmb[nloc * 17 + o] = emb[sp * CC + o];
    __syncthreads();

    float h1 = b1[o];
#pragma unroll
    for (int k = 0; k < CC; k++) h1 = fmaf(sEmb[nloc * 17 + k], W1[k * CC + o], h1);
#pragma unroll
    for (int k = 0; k < CC; k++) h1 = fmaf(sFeat[nloc * 17 + k], W1[(CC + k) * CC + o], h1);
    sH[nloc * 17 + o] = siluf(h1);
    __syncthreads();

    float h2 = b2[o];
#pragma unroll
    for (int k = 0; k < CC; k++) h2 = fmaf(sH[nloc * 17 + k], W2[k * CC + o], h2);
    h2 = siluf(h2);

    float part = h2 * W3[o];
#pragma unroll
    for (int off = 8; off > 0; off >>= 1)
        part += __shfl_down_sync(0xffffffffu, part, off, 16);
    if (o == 0) sRed[nloc] = part + b3[0] + sCoul[nloc];
    __syncthreads();
    if (tid == 0) {
        float acc = 0.f;
#pragma unroll
        for (int k = 0; k < 16; k++) acc += sRed[k];
        atomicAdd(out, acc);
    }
}

// ---------------- host launch ----------------
extern "C" void kernel_launch(void* const* d_in, const int* in_sizes, int n_in,
                              void* d_out, int out_size) {
    const int* species  = (const int*)d_in[0];
    const int* src      = (const int*)d_in[1];
    const int* dst      = (const int*)d_in[2];
    const float* rel_pos = (const float*)d_in[3];
    const float* emb    = (const float*)d_in[4];
    const float* kv_W1  = (const float*)d_in[5];
    const float* kv_b1  = (const float*)d_in[6];
    const float* kv_W2  = (const float*)d_in[7];
    const float* kv_b2  = (const float*)d_in[8];
    const float* kv_W3  = (const float*)d_in[9];
    const float* kv_b3  = (const float*)d_in[10];
    const float* Wq     = (const float*)d_in[11];
    const float* Wproj  = (const float*)d_in[12];
    const float* fin_W1 = (const float*)d_in[13];
    const float* fin_b1 = (const float*)d_in[14];
    const float* fin_W2 = (const float*)d_in[15];
    const float* fin_b2 = (const float*)d_in[16];
    const float* fin_W3 = (const float*)d_in[17];
    const float* fin_b3 = (const float*)d_in[18];
    const float* Wself  = (const float*)d_in[19];
    const float* mlp_W1 = (const float*)d_in[20];
    const float* mlp_b1 = (const float*)d_in[21];
    const float* mlp_W2 = (const float*)d_in[22];
    const float* mlp_b2 = (const float*)d_in[23];
    const float* mlp_W3 = (const float*)d_in[24];
    const float* mlp_b3 = (const float*)d_in[25];
    float* out = (float*)d_out;

    const int EB = EE / 256;
    const int NB = NN / 256;
    const int LB = NN / 32;
    const int EB2 = EE / 128;

    k_init_nodes<<<NB, 256>>>(species, emb, out);
    k_hist<<<EB, 256>>>(src, dst);
    k_scan<<<2, 1024>>>();
    k_scatter<<<EB, 256>>>(src, dst, rel_pos, species);

    k_node_layer<<<LB, 256>>>(0, nullptr,
                              Wq, kv_W3, kv_b3, kv_W1, kv_b1, nullptr);
    for (int l = 0; l < 4; l++) {
        k_edge<false><<<EB2, 128>>>(kv_W1 + (size_t)l * CC * MIDD,
                                    kv_W2 + (size_t)l * MIDD * MIDD,
                                    kv_b2 + (size_t)l * MIDD);
        if (l < 3) {
            k_node_layer<<<LB, 256>>>(1,
                Wproj + (size_t)l * CC * 24,
                Wq + (size_t)(l + 1) * HH * CC,
                kv_W3 + (size_t)(l + 1) * MIDD * 256,
                kv_b3 + (size_t)(l + 1) * 256,
                kv_W1 + (size_t)(l + 1) * CC * MIDD,
                kv_b1 + (size_t)(l + 1) * MIDD,
                nullptr);
        } else {
            k_node_layer<<<LB, 256>>>(2,
                Wproj + (size_t)l * CC * 24,
                nullptr,
                fin_W3, fin_b3, fin_W1, fin_b1, Wself);
        }
    }
    k_edge<true><<<EB2, 128>>>(fin_W1, fin_W2, fin_b2);
    k_final<<<NN / 16, 256>>>(species, emb, mlp_W1, mlp_b1, mlp_W2, mlp_b2,
                              mlp_W3, mlp_b3, out);
}

// round 5
// speedup vs baseline: 1.1197x; 1.1197x over previous
#include <cuda_runtime.h>
#include <math.h>

#define NN 32768
#define EE 524288
#define CC 16
#define MIDD 32
#define HH 8
#define Y0F 0.28209479177387814f
#define CUTOFFF 4.6f
#define KCOULF 0.529f

typedef unsigned long long ull;

// ---------------- device scratch ----------------
__device__ __align__(16) float g_x[NN * CC];
__device__ __align__(16) float g_S[NN * CC];
__device__ __align__(16) float g_q[NN * HH];
__device__ __align__(16) float g_u[NN * MIDD];
__device__ __align__(16) float g_P[NN * 512];    // pair-interleaved: ull idx = mq*32 + j*4 + r  -> (P[m][j], P[m][j+8]), m=mq*4+r
__device__ __align__(16) float g_PB[NN * CC];    // pair-interleaved: n*16 + j*2 + t
__device__ __align__(16) float g_feats[NN * CC];
__device__ __align__(16) float g_vl[EE * CC];    // dst-sorted: [pd][j][2] = {val, logit}
__device__ __align__(16) float g_msgD[EE * CC];  // dst-sorted, pair-interleaved
__device__ float g_distS[EE];
__device__ float g_scaleS[EE];
__device__ float g_scaleD[EE];
__device__ float g_contribD[EE];
__device__ int g_srcS[EE];
__device__ int g_dstS[EE];
__device__ int g_posd[EE];
__device__ int g_csrc[NN], g_cdst[NN];
__device__ int g_rdst[NN + 1];
__device__ int g_cursrc[NN], g_curdst[NN];
__device__ int g_rsrc_unused[NN + 1];

// ---------------- f32x2 helpers ----------------
__device__ __forceinline__ ull pack2(float a, float b) {
    ull r;
    asm("mov.b64 %0, {%1, %2};" : "=l"(r) : "f"(a), "f"(b));
    return r;
}
__device__ __forceinline__ ull fma2(ull a, ull b, ull c) {
    ull d;
    asm("fma.rn.f32x2 %0, %1, %2, %3;" : "=l"(d) : "l"(a), "l"(b), "l"(c));
    return d;
}
__device__ __forceinline__ void unpack2(ull v, float& lo, float& hi) {
    asm("mov.b64 {%0, %1}, %2;" : "=f"(lo), "=f"(hi) : "l"(v));
}

// ---------------- init: node init + edge histogram (counters zeroed by prior k_scan) ----------------
__global__ void k_init(const int* __restrict__ species, const float* __restrict__ emb,
                       float* __restrict__ out,
                       const int* __restrict__ src, const int* __restrict__ dst) {
    int e = blockIdx.x * 256 + threadIdx.x;
    if (e < NN) {
        int sp = species[e] - 1;
#pragma unroll
        for (int c = 0; c < CC; c++) {
            g_x[e * CC + c] = emb[sp * CC + c];
            g_S[e * CC + c] = 0.f;
        }
        if (e == 0) out[0] = 0.f;
    }
    atomicAdd(&g_csrc[src[e]], 1);
    atomicAdd(&g_cdst[dst[e]], 1);
}

// ---------------- scan (also re-zeroes counters for next run) ----------------
__global__ void k_scan() {
    const int T = 1024, PER = NN / 1024;
    __shared__ int part[T];
    int* cnt = blockIdx.x == 0 ? g_csrc : g_cdst;
    int* row = blockIdx.x == 0 ? g_rsrc_unused : g_rdst;
    int* cur = blockIdx.x == 0 ? g_cursrc : g_curdst;
    int t = threadIdx.x;
    int base = t * PER;
    int loc[PER];
    int s = 0;
#pragma unroll
    for (int i = 0; i < PER; i++) {
        loc[i] = cnt[base + i];
        cnt[base + i] = 0;           // reset for next execution
        s += loc[i];
    }
    part[t] = s;
    __syncthreads();
    for (int off = 1; off < T; off <<= 1) {
        int v = (t >= off) ? part[t - off] : 0;
        __syncthreads();
        part[t] += v;
        __syncthreads();
    }
    int run = part[t] - s;
#pragma unroll
    for (int i = 0; i < PER; i++) {
        row[base + i] = run;
        cur[base + i] = run;
        run += loc[i];
    }
    if (t == T - 1) row[NN] = run;
}

// ---------------- shared node-prep helpers ----------------
#define W3P_STRIDE 1036

__device__ __forceinline__ void load_node_weights(
    int tid, const float* __restrict__ W3, const float* __restrict__ b3,
    const float* __restrict__ W1n, const float* __restrict__ b1n,
    const float* __restrict__ Wq, const float* __restrict__ Wself,
    float* sW3p, float* sW1, float* sWq, float* sb3, float* sb1, float* sWself) {
    for (int idx = tid; idx < MIDD * 256; idx += 256) {
        int m = idx >> 8, k = idx & 255;
        int o = k >> 4, i = k & 15;
        sW3p[(o & 7) * W3P_STRIDE + i * 64 + m * 2 + (o >> 3)] = W3[idx];
    }
    for (int idx = tid; idx < CC * MIDD; idx += 256) sW1[idx] = W1n[idx];
    if (Wq && tid < HH * CC) sWq[tid] = Wq[tid];
    sb3[tid] = b3[tid];
    if (tid < MIDD) sb1[tid] = b1n[tid];
    if (Wself && tid < CC * CC) sWself[tid] = Wself[tid];
}

// q/u/PB/feats/P computation for node n; lane j owns o-pair (j, j+8)
__device__ __forceinline__ void node_prep(
    int n, int nloc, int j, bool do_q, bool do_feats,
    const float* sW3p, const float* sW1, const float* sWq,
    const float* sb3, const float* sb1, const float* sWself,
    const float* sXn, const float* sSn) {
    if (do_q) {
        float qa = 0.f;
#pragma unroll
        for (int c = 0; c < CC; c++) qa = fmaf(sWq[j * CC + c], sXn[nloc * CC + c], qa);
        g_q[n * HH + j] = qa;
    }
    {
        float u0 = sb1[j], u1 = sb1[j + 8], u2 = sb1[j + 16], u3 = sb1[j + 24];
#pragma unroll
        for (int c = 0; c < CC; c++) {
            float sv = sSn[nloc * CC + c];
            u0 = fmaf(sv, sW1[c * MIDD + j], u0);
            u1 = fmaf(sv, sW1[c * MIDD + j + 8], u1);
            u2 = fmaf(sv, sW1[c * MIDD + j + 16], u2);
            u3 = fmaf(sv, sW1[c * MIDD + j + 24], u3);
        }
        g_u[n * MIDD + j] = u0;
        g_u[n * MIDD + j + 8] = u1;
        g_u[n * MIDD + j + 16] = u2;
        g_u[n * MIDD + j + 24] = u3;
    }
    {
        float pb0 = 0.f, pb1 = 0.f;
#pragma unroll
        for (int i = 0; i < CC; i++) {
            float xv = sXn[nloc * CC + i];
            pb0 = fmaf(sb3[j * CC + i], xv, pb0);
            pb1 = fmaf(sb3[(j + 8) * CC + i], xv, pb1);
        }
        g_PB[n * CC + j * 2] = pb0;
        g_PB[n * CC + j * 2 + 1] = pb1;
    }
    if (do_feats) {
        float f0 = 0.f, f1 = 0.f;
#pragma unroll
        for (int i = 0; i < CC; i++) {
            float xv = sXn[nloc * CC + i];
            f0 = fmaf(sWself[j * CC + i], xv, f0);
            f1 = fmaf(sWself[(j + 8) * CC + i], xv, f1);
        }
        g_feats[n * CC + j] = f0;
        g_feats[n * CC + 8 + j] = f1;
    }
    {
        ull acc[8][4];
#pragma unroll
        for (int mq = 0; mq < 8; mq++)
#pragma unroll
            for (int r = 0; r < 4; r++) acc[mq][r] = 0ULL;
#pragma unroll
        for (int i = 0; i < CC; i++) {
            float xv = sXn[nloc * CC + i];
            ull xx = pack2(xv, xv);
            const ull* wp = (const ull*)&sW3p[j * W3P_STRIDE + i * 64];
#pragma unroll
            for (int mq = 0; mq < 8; mq++) {
                acc[mq][0] = fma2(xx, wp[mq * 4 + 0], acc[mq][0]);
                acc[mq][1] = fma2(xx, wp[mq * 4 + 1], acc[mq][1]);
                acc[mq][2] = fma2(xx, wp[mq * 4 + 2], acc[mq][2]);
                acc[mq][3] = fma2(xx, wp[mq * 4 + 3], acc[mq][3]);
            }
        }
        float* Pn = g_P + (size_t)n * 512;
#pragma unroll
        for (int mq = 0; mq < 8; mq++) {
            *(ulonglong2*)(Pn + mq * 64 + j * 8)     = make_ulonglong2(acc[mq][0], acc[mq][1]);
            *(ulonglong2*)(Pn + mq * 64 + j * 8 + 4) = make_ulonglong2(acc[mq][2], acc[mq][3]);
        }
    }
}

// ---------------- fused prep: blocks [0,2048) scatter edges; [2048,3072) node prep layer 0 ----------------
__global__ void __launch_bounds__(256)
k_prep(const int* __restrict__ src, const int* __restrict__ dst,
       const float* __restrict__ rel_pos, const int* __restrict__ species,
       const float* __restrict__ Wq, const float* __restrict__ W3,
       const float* __restrict__ b3, const float* __restrict__ W1n,
       const float* __restrict__ b1n) {
    __shared__ float sW3p[8 * W3P_STRIDE];
    __shared__ float sW1[CC * MIDD];
    __shared__ float sWq[HH * CC];
    __shared__ float sb3[256];
    __shared__ float sb1[MIDD];
    __shared__ float sXn[32 * CC];
    __shared__ float sSn[32 * CC];
    int tid = threadIdx.x;

    if (blockIdx.x < 2048) {
        int e = blockIdx.x * 256 + tid;
        int s = src[e], d = dst[e];
        float px = rel_pos[e * 3 + 0], py = rel_pos[e * 3 + 1], pz = rel_pos[e * 3 + 2];
        float dist = sqrtf(px * px + py * py + pz * pz);
        float xc = dist / CUTOFFF;
        bool in_cut = dist < CUTOFFF;
        float x2 = in_cut ? fminf(xc * xc, 1.f - 1e-6f) : 0.f;
        float scale = in_cut ? expf(3.f - 3.f / (1.f - x2)) : 0.f;

        int ps = atomicAdd(&g_cursrc[s], 1);
        int pd = atomicAdd(&g_curdst[d], 1);
        g_srcS[ps] = s;
        g_dstS[ps] = d;
        g_posd[ps] = pd;
        g_distS[ps] = dist;
        g_scaleS[ps] = scale;
        g_scaleD[pd] = scale;

        float Zu = (float)species[s];
        float Zv = (float)species[d];
        float raw = KCOULF * Zu * Zv / (2.f * dist);
        float au = 0.8854f * 0.529f / (__powf(Zu, 0.23f) + __powf(Zv, 0.23f));
        float xx = dist / au;
        float screen = 0.1818f * __expf(-3.2f * xx) + 0.5099f * __expf(-0.9423f * xx)
                     + 0.2802f * __expf(-0.4028f * xx) + 0.02817f * __expf(-0.2016f * xx);
        g_contribD[pd] = raw * screen * scale;
        return;
    }

    int blk = blockIdx.x - 2048;
    load_node_weights(tid, W3, b3, W1n, b1n, Wq, nullptr,
                      sW3p, sW1, sWq, sb3, sb1, nullptr);
    int nloc = tid >> 3, j = tid & 7;
    int n = blk * 32 + nloc;
    sXn[nloc * CC + j] = g_x[n * CC + j];
    sXn[nloc * CC + 8 + j] = g_x[n * CC + 8 + j];
    sSn[nloc * CC + j] = 0.f;
    sSn[nloc * CC + 8 + j] = 0.f;
    __syncthreads();
    node_prep(n, nloc, j, true, false, sW3p, sW1, sWq, sb3, sb1, nullptr, sXn, sSn);
}

// ---------------- node layer: attention + Wproj + prep next weights ----------------
// mode 1: prep next kv layer (q);  mode 2: prep fin weights + Wself feats (no q)
__global__ void __launch_bounds__(256)
k_node_layer(int mode,
             const float* __restrict__ Wproj,
             const float* __restrict__ Wq,
             const float* __restrict__ W3,
             const float* __restrict__ b3,
             const float* __restrict__ W1n,
             const float* __restrict__ b1n,
             const float* __restrict__ Wself) {
    __shared__ float sW3p[8 * W3P_STRIDE];
    __shared__ float sW1[CC * MIDD];
    __shared__ float sWq[HH * CC];
    __shared__ float sWproj[CC * 24];
    __shared__ float sb3[256];
    __shared__ float sb1[MIDD];
    __shared__ float sWself[CC * CC];
    __shared__ float sAgg[32 * HH];
    __shared__ float sXold[32 * CC];
    __shared__ float sXn[32 * CC];
    __shared__ float sSn[32 * CC];

    int tid = threadIdx.x;
    int nloc = tid >> 3, j = tid & 7;
    int n = blockIdx.x * 32 + nloc;

    load_node_weights(tid, W3, b3, W1n, b1n,
                      mode != 2 ? Wq : nullptr,
                      mode == 2 ? Wself : nullptr,
                      sW3p, sW1, sWq, sb3, sb1, sWself);
    for (int idx = tid; idx < CC * 24; idx += 256) sWproj[idx] = Wproj[idx];

    {
        int beg = g_rdst[n], end = g_rdst[n + 1];
        float mx = -INFINITY;
        for (int i = beg; i < end; i++) {
            float2 vl = *(const float2*)(g_vl + (size_t)i * CC + j * 2);
            mx = fmaxf(mx, vl.y);
        }
        float num = 0.f, den = 0.f;
        for (int i = beg; i < end; i++) {
            float2 vl = *(const float2*)(g_vl + (size_t)i * CC + j * 2);
            float w = g_scaleD[i] * __expf(vl.y - mx);
            den += w;
            num = fmaf(w, vl.x, num);
        }
        sAgg[nloc * HH + j] = num / fmaxf(den, 1e-20f);
        sXold[nloc * CC + j] = g_x[n * CC + j];
        sXold[nloc * CC + 8 + j] = g_x[n * CC + 8 + j];
        __syncthreads();
        float xn0 = 0.f, xn1 = 0.f;
#pragma unroll
        for (int k = 0; k < 8; k++) {
            float a = sAgg[nloc * HH + k];
            xn0 = fmaf(sWproj[j * 24 + k], a, xn0);
            xn1 = fmaf(sWproj[(j + 8) * 24 + k], a, xn1);
        }
#pragma unroll
        for (int k = 0; k < CC; k++) {
            float xo = sXold[nloc * CC + k];
            xn0 = fmaf(sWproj[j * 24 + 8 + k], xo, xn0);
            xn1 = fmaf(sWproj[(j + 8) * 24 + 8 + k], xo, xn1);
        }
        float s0 = g_S[n * CC + j] + xn0;
        float s1 = g_S[n * CC + 8 + j] + xn1;
        g_x[n * CC + j] = xn0;     g_x[n * CC + 8 + j] = xn1;
        g_S[n * CC + j] = s0;      g_S[n * CC + 8 + j] = s1;
        sXn[nloc * CC + j] = xn0;  sXn[nloc * CC + 8 + j] = xn1;
        sSn[nloc * CC + j] = s0;   sSn[nloc * CC + 8 + j] = s1;
        __syncthreads();
    }

    node_prep(n, nloc, j, mode != 2, mode == 2,
              sW3p, sW1, sWq, sb3, sb1, sWself, sXn, sSn);
}

// ---------------- edge kernel: thread-per-edge, all f32x2, src-sorted L1 dedup ----------------
template <bool FIN>
__global__ void __launch_bounds__(256)
k_edge(const float* __restrict__ W1, const float* __restrict__ W2,
       const float* __restrict__ b2) {
    __shared__ ull sW2p[512];   // [i2][jp]
    __shared__ float sw15[MIDD];
    __shared__ ull sB2p[16];
    int tid = threadIdx.x;
    for (int i = tid; i < 512; i += 256) sW2p[i] = ((const ull*)W2)[i];
    if (tid < MIDD) sw15[tid] = W1[15 * MIDD + tid];
    if (tid < 16) sB2p[tid] = ((const ull*)b2)[tid];
    __syncthreads();

    int e = blockIdx.x * 256 + tid;
    int s = g_srcS[e];
    float dist = g_distS[e];
    float bs = Y0F * g_scaleS[e];
    int pd = g_posd[e];

    // radial MLP (u-trick): h1 = relu(u[s] + dist*w15); h2 = relu(W2^T h1 + b2)
    float h2[MIDD];
    {
        float h1[MIDD];
        const float4* up = (const float4*)(g_u + (size_t)s * MIDD);
#pragma unroll
        for (int t = 0; t < 8; t++) {
            float4 uv = up[t];
            h1[4 * t + 0] = fmaxf(fmaf(dist, sw15[4 * t + 0], uv.x), 0.f);
            h1[4 * t + 1] = fmaxf(fmaf(dist, sw15[4 * t + 1], uv.y), 0.f);
            h1[4 * t + 2] = fmaxf(fmaf(dist, sw15[4 * t + 2], uv.z), 0.f);
            h1[4 * t + 3] = fmaxf(fmaf(dist, sw15[4 * t + 3], uv.w), 0.f);
        }
        ull acc[16];
#pragma unroll
        for (int jp = 0; jp < 16; jp++) acc[jp] = sB2p[jp];
#pragma unroll
        for (int i2 = 0; i2 < MIDD; i2++) {
            ull xx = pack2(h1[i2], h1[i2]);
#pragma unroll
            for (int jp = 0; jp < 16; jp++)
                acc[jp] = fma2(xx, sW2p[i2 * 16 + jp], acc[jp]);
        }
#pragma unroll
        for (int jp = 0; jp < 16; jp++) {
            float lo, hi;
            unpack2(acc[jp], lo, hi);
            h2[2 * jp] = fmaxf(lo, 0.f);
            h2[2 * jp + 1] = fmaxf(hi, 0.f);
        }
    }

    // contraction: kacc[j] = (kv[j], kv[j+8]);  P lines dedup across warp (sorted src)
    ull kacc[8];
    {
        const ulonglong2* pbp = (const ulonglong2*)(g_PB + (size_t)s * CC);
#pragma unroll
        for (int t = 0; t < 4; t++) {
            ulonglong2 pb = pbp[t];
            kacc[2 * t] = pb.x;
            kacc[2 * t + 1] = pb.y;
        }
        const ull* Pp = (const ull*)(g_P + (size_t)s * 512);
#pragma unroll
        for (int mq = 0; mq < 8; mq++) {
            ull x0 = pack2(h2[mq * 4 + 0], h2[mq * 4 + 0]);
            ull x1 = pack2(h2[mq * 4 + 1], h2[mq * 4 + 1]);
            ull x2 = pack2(h2[mq * 4 + 2], h2[mq * 4 + 2]);
            ull x3 = pack2(h2[mq * 4 + 3], h2[mq * 4 + 3]);
#pragma unroll
            for (int j = 0; j < 8; j++) {
                ulonglong2 pA = *(const ulonglong2*)(Pp + mq * 32 + j * 4);
                ulonglong2 pB = *(const ulonglong2*)(Pp + mq * 32 + j * 4 + 2);
                kacc[j] = fma2(x0, pA.x, kacc[j]);
                kacc[j] = fma2(x1, pA.y, kacc[j]);
                kacc[j] = fma2(x2, pB.x, kacc[j]);
                kacc[j] = fma2(x3, pB.y, kacc[j]);
            }
        }
    }

    if (!FIN) {
        int d = g_dstS[e];
        const float4* qp = (const float4*)(g_q + (size_t)d * HH);
        float4 qa = qp[0], qb = qp[1];
        float qv[8] = {qa.x, qa.y, qa.z, qa.w, qb.x, qb.y, qb.z, qb.w};
        float4 ov[4];
#pragma unroll
        for (int t = 0; t < 4; t++) {
            float v0, k0, v1, k1;
            unpack2(kacc[2 * t], v0, k0);
            unpack2(kacc[2 * t + 1], v1, k1);
            ov[t] = make_float4(v0 * bs, k0 * bs * qv[2 * t],
                                v1 * bs, k1 * bs * qv[2 * t + 1]);
        }
        float4* dp = (float4*)(g_vl + (size_t)pd * CC);
        dp[0] = ov[0]; dp[1] = ov[1]; dp[2] = ov[2]; dp[3] = ov[3];
    } else {
        float4 ov[4];
#pragma unroll
        for (int t = 0; t < 4; t++) {
            float a0, b0, a1, b1;
            unpack2(kacc[2 * t], a0, b0);
            unpack2(kacc[2 * t + 1], a1, b1);
            ov[t] = make_float4(a0 * bs, b0 * bs, a1 * bs, b1 * bs);
        }
        float4* dp = (float4*)(g_msgD + (size_t)pd * CC);
        dp[0] = ov[0]; dp[1] = ov[1]; dp[2] = ov[2]; dp[3] = ov[3];
    }
}

// ---------------- final ----------------
__device__ __forceinline__ float siluf(float x) { return x / (1.f + __expf(-x)); }

__global__ void k_final(const int* __restrict__ species, const float* __restrict__ emb,
                        const float* __restrict__ W1, const float* __restrict__ b1,
                        const float* __restrict__ W2, const float* __restrict__ b2,
                        const float* __restrict__ W3, const float* __restrict__ b3,
                        float* __restrict__ out) {
    __shared__ float sFeat[16 * 17];
    __shared__ float sEmb[16 * 17];
    __shared__ float sH[16 * 17];
    __shared__ float sCoul[16];
    __shared__ float sRed[16];
    int tid = threadIdx.x;
    int nloc = tid >> 4, o = tid & 15;
    int n = blockIdx.x * 16 + nloc;
    int beg = g_rdst[n], end = g_rdst[n + 1];
    int o2 = (o < 8) ? o * 2 : (o - 8) * 2 + 1;   // pair-interleaved msgD
    float f = g_feats[n * CC + o];
    for (int i = beg; i < end; i++) f += g_msgD[(size_t)i * CC + o2];
    sFeat[nloc * 17 + o] = f;
    if (o == 0) {
        float c = 0.f;
        for (int i = beg; i < end; i++) c += g_contribD[i];
        sCoul[nloc] = c;
    }
    int sp = species[n] - 1;
    sEmb[nloc * 17 + o] = emb[sp * CC + o];
    __syncthreads();

    float h1 = b1[o];
#pragma unroll
    for (int k = 0; k < CC; k++) h1 = fmaf(sEmb[nloc * 17 + k], W1[k * CC + o], h1);
#pragma unroll
    for (int k = 0; k < CC; k++) h1 = fmaf(sFeat[nloc * 17 + k], W1[(CC + k) * CC + o], h1);
    sH[nloc * 17 + o] = siluf(h1);
    __syncthreads();

    float h2 = b2[o];
#pragma unroll
    for (int k = 0; k < CC; k++) h2 = fmaf(sH[nloc * 17 + k], W2[k * CC + o], h2);
    h2 = siluf(h2);

    float part = h2 * W3[o];
#pragma unroll
    for (int off = 8; off > 0; off >>= 1)
        part += __shfl_down_sync(0xffffffffu, part, off, 16);
    if (o == 0) sRed[nloc] = part + b3[0] + sCoul[nloc];
    __syncthreads();
    if (tid == 0) {
        float acc = 0.f;
#pragma unroll
        for (int k = 0; k < 16; k++) acc += sRed[k];
        atomicAdd(out, acc);
    }
}

// ---------------- host launch ----------------
extern "C" void kernel_launch(void* const* d_in, const int* in_sizes, int n_in,
                              void* d_out, int out_size) {
    const int* species  = (const int*)d_in[0];
    const int* src      = (const int*)d_in[1];
    const int* dst      = (const int*)d_in[2];
    const float* rel_pos = (const float*)d_in[3];
    const float* emb    = (const float*)d_in[4];
    const float* kv_W1  = (const float*)d_in[5];
    const float* kv_b1  = (const float*)d_in[6];
    const float* kv_W2  = (const float*)d_in[7];
    const float* kv_b2  = (const float*)d_in[8];
    const float* kv_W3  = (const float*)d_in[9];
    const float* kv_b3  = (const float*)d_in[10];
    const float* Wq     = (const float*)d_in[11];
    const float* Wproj  = (const float*)d_in[12];
    const float* fin_W1 = (const float*)d_in[13];
    const float* fin_b1 = (const float*)d_in[14];
    const float* fin_W2 = (const float*)d_in[15];
    const float* fin_b2 = (const float*)d_in[16];
    const float* fin_W3 = (const float*)d_in[17];
    const float* fin_b3 = (const float*)d_in[18];
    const float* Wself  = (const float*)d_in[19];
    const float* mlp_W1 = (const float*)d_in[20];
    const float* mlp_b1 = (const float*)d_in[21];
    const float* mlp_W2 = (const float*)d_in[22];
    const float* mlp_b2 = (const float*)d_in[23];
    const float* mlp_W3 = (const float*)d_in[24];
    const float* mlp_b3 = (const float*)d_in[25];
    float* out = (float*)d_out;

    const int EB = EE / 256;   // 2048
    const int LB = NN / 32;    // 1024

    k_init<<<EB, 256>>>(species, emb, out, src, dst);
    k_scan<<<2, 1024>>>();
    k_prep<<<EB + LB, 256>>>(src, dst, rel_pos, species,
                             Wq, kv_W3, kv_b3, kv_W1, kv_b1);

    for (int l = 0; l < 4; l++) {
        k_edge<false><<<EB, 256>>>(kv_W1 + (size_t)l * CC * MIDD,
                                   kv_W2 + (size_t)l * MIDD * MIDD,
                                   kv_b2 + (size_t)l * MIDD);
        if (l < 3) {
            k_node_layer<<<LB, 256>>>(1,
                Wproj + (size_t)l * CC * 24,
                Wq + (size_t)(l + 1) * HH * CC,
                kv_W3 + (size_t)(l + 1) * MIDD * 256,
                kv_b3 + (size_t)(l + 1) * 256,
                kv_W1 + (size_t)(l + 1) * CC * MIDD,
                kv_b1 + (size_t)(l + 1) * MIDD,
                nullptr);
        } else {
            k_node_layer<<<LB, 256>>>(2,
                Wproj + (size_t)l * CC * 24,
                nullptr,
                fin_W3, fin_b3, fin_W1, fin_b1, Wself);
        }
    }
    k_edge<true><<<EB, 256>>>(fin_W1, fin_W2, fin_b2);
    k_final<<<NN / 16, 256>>>(species, emb, mlp_W1, mlp_b1, mlp_W2, mlp_b2,
                              mlp_W3, mlp_b3, out);
}

// round 6
// speedup vs baseline: 1.1208x; 1.0010x over previous
#include <cuda_runtime.h>
#include <math.h>

#define NN 32768
#define EE 524288
#define CC 16
#define MIDD 32
#define HH 8
#define Y0F 0.28209479177387814f
#define CUTOFFF 4.6f
#define KCOULF 0.529f

typedef unsigned long long ull;

// ---------------- device scratch ----------------
__device__ __align__(16) float g_x[NN * CC];
__device__ __align__(16) float g_S[NN * CC];
__device__ __align__(16) float g_q[NN * HH];
__device__ __align__(16) float g_u[NN * MIDD];
__device__ __align__(16) float g_P[NN * 512];    // pair-interleaved
__device__ __align__(16) float g_PB[NN * CC];    // pair-interleaved
__device__ __align__(16) float g_feats[NN * CC];
__device__ __align__(16) float g_vk[EE * CC];    // SRC-sorted: [e][j][2] = {val(bs*kv[j]), key(bs*kv[j+8])}
__device__ float g_distS[EE];
__device__ float g_scaleS[EE];
__device__ float g_scaleD[EE];
__device__ float g_contribD[EE];
__device__ int g_srcS[EE];
__device__ int g_eidxD[EE];                      // dst-order -> src-order index
__device__ int g_csrc[NN], g_cdst[NN];
__device__ int g_rdst[NN + 1];
__device__ int g_cursrc[NN], g_curdst[NN];
__device__ int g_rsrc_unused[NN + 1];

// ---------------- f32x2 helpers ----------------
__device__ __forceinline__ ull pack2(float a, float b) {
    ull r;
    asm("mov.b64 %0, {%1, %2};" : "=l"(r) : "f"(a), "f"(b));
    return r;
}
__device__ __forceinline__ ull fma2(ull a, ull b, ull c) {
    ull d;
    asm("fma.rn.f32x2 %0, %1, %2, %3;" : "=l"(d) : "l"(a), "l"(b), "l"(c));
    return d;
}
__device__ __forceinline__ void unpack2(ull v, float& lo, float& hi) {
    asm("mov.b64 {%0, %1}, %2;" : "=f"(lo), "=f"(hi) : "l"(v));
}

// ---------------- init: node init + edge histogram (counters zeroed by prior k_scan) ----------------
__global__ void k_init(const int* __restrict__ species, const float* __restrict__ emb,
                       float* __restrict__ out,
                       const int* __restrict__ src, const int* __restrict__ dst) {
    int e = blockIdx.x * 256 + threadIdx.x;
    if (e < NN) {
        int sp = species[e] - 1;
#pragma unroll
        for (int c = 0; c < CC; c++) {
            g_x[e * CC + c] = emb[sp * CC + c];
            g_S[e * CC + c] = 0.f;
        }
        if (e == 0) out[0] = 0.f;
    }
    atomicAdd(&g_csrc[src[e]], 1);
    atomicAdd(&g_cdst[dst[e]], 1);
}

// ---------------- scan (also re-zeroes counters for next graph replay) ----------------
__global__ void k_scan() {
    const int T = 1024, PER = NN / 1024;
    __shared__ int part[T];
    int* cnt = blockIdx.x == 0 ? g_csrc : g_cdst;
    int* row = blockIdx.x == 0 ? g_rsrc_unused : g_rdst;
    int* cur = blockIdx.x == 0 ? g_cursrc : g_curdst;
    int t = threadIdx.x;
    int base = t * PER;
    int loc[PER];
    int s = 0;
#pragma unroll
    for (int i = 0; i < PER; i++) {
        loc[i] = cnt[base + i];
        cnt[base + i] = 0;
        s += loc[i];
    }
    part[t] = s;
    __syncthreads();
    for (int off = 1; off < T; off <<= 1) {
        int v = (t >= off) ? part[t - off] : 0;
        __syncthreads();
        part[t] += v;
        __syncthreads();
    }
    int run = part[t] - s;
#pragma unroll
    for (int i = 0; i < PER; i++) {
        row[base + i] = run;
        cur[base + i] = run;
        run += loc[i];
    }
    if (t == T - 1) row[NN] = run;
}

// ---------------- shared node-prep helpers ----------------
#define W3P_STRIDE 1036

__device__ __forceinline__ void load_node_weights(
    int tid, const float* __restrict__ W3, const float* __restrict__ b3,
    const float* __restrict__ W1n, const float* __restrict__ b1n,
    const float* __restrict__ Wq, const float* __restrict__ Wself,
    float* sW3p, float* sW1, float* sWq, float* sb3, float* sb1, float* sWself) {
    for (int idx = tid; idx < MIDD * 256; idx += 256) {
        int m = idx >> 8, k = idx & 255;
        int o = k >> 4, i = k & 15;
        sW3p[(o & 7) * W3P_STRIDE + i * 64 + m * 2 + (o >> 3)] = W3[idx];
    }
    for (int idx = tid; idx < CC * MIDD; idx += 256) sW1[idx] = W1n[idx];
    if (Wq && tid < HH * CC) sWq[tid] = Wq[tid];
    sb3[tid] = b3[tid];
    if (tid < MIDD) sb1[tid] = b1n[tid];
    if (Wself && tid < CC * CC) sWself[tid] = Wself[tid];
}

__device__ __forceinline__ void node_prep(
    int n, int nloc, int j, bool do_q, bool do_feats,
    const float* sW3p, const float* sW1, const float* sWq,
    const float* sb3, const float* sb1, const float* sWself,
    const float* sXn, const float* sSn) {
    if (do_q) {
        float qa = 0.f;
#pragma unroll
        for (int c = 0; c < CC; c++) qa = fmaf(sWq[j * CC + c], sXn[nloc * CC + c], qa);
        g_q[n * HH + j] = qa;
    }
    {
        float u0 = sb1[j], u1 = sb1[j + 8], u2 = sb1[j + 16], u3 = sb1[j + 24];
#pragma unroll
        for (int c = 0; c < CC; c++) {
            float sv = sSn[nloc * CC + c];
            u0 = fmaf(sv, sW1[c * MIDD + j], u0);
            u1 = fmaf(sv, sW1[c * MIDD + j + 8], u1);
            u2 = fmaf(sv, sW1[c * MIDD + j + 16], u2);
            u3 = fmaf(sv, sW1[c * MIDD + j + 24], u3);
        }
        g_u[n * MIDD + j] = u0;
        g_u[n * MIDD + j + 8] = u1;
        g_u[n * MIDD + j + 16] = u2;
        g_u[n * MIDD + j + 24] = u3;
    }
    {
        float pb0 = 0.f, pb1 = 0.f;
#pragma unroll
        for (int i = 0; i < CC; i++) {
            float xv = sXn[nloc * CC + i];
            pb0 = fmaf(sb3[j * CC + i], xv, pb0);
            pb1 = fmaf(sb3[(j + 8) * CC + i], xv, pb1);
        }
        g_PB[n * CC + j * 2] = pb0;
        g_PB[n * CC + j * 2 + 1] = pb1;
    }
    if (do_feats) {
        float f0 = 0.f, f1 = 0.f;
#pragma unroll
        for (int i = 0; i < CC; i++) {
            float xv = sXn[nloc * CC + i];
            f0 = fmaf(sWself[j * CC + i], xv, f0);
            f1 = fmaf(sWself[(j + 8) * CC + i], xv, f1);
        }
        g_feats[n * CC + j] = f0;
        g_feats[n * CC + 8 + j] = f1;
    }
    {
        ull acc[8][4];
#pragma unroll
        for (int mq = 0; mq < 8; mq++)
#pragma unroll
            for (int r = 0; r < 4; r++) acc[mq][r] = 0ULL;
#pragma unroll
        for (int i = 0; i < CC; i++) {
            float xv = sXn[nloc * CC + i];
            ull xx = pack2(xv, xv);
            const ull* wp = (const ull*)&sW3p[j * W3P_STRIDE + i * 64];
#pragma unroll
            for (int mq = 0; mq < 8; mq++) {
                acc[mq][0] = fma2(xx, wp[mq * 4 + 0], acc[mq][0]);
                acc[mq][1] = fma2(xx, wp[mq * 4 + 1], acc[mq][1]);
                acc[mq][2] = fma2(xx, wp[mq * 4 + 2], acc[mq][2]);
                acc[mq][3] = fma2(xx, wp[mq * 4 + 3], acc[mq][3]);
            }
        }
        float* Pn = g_P + (size_t)n * 512;
#pragma unroll
        for (int mq = 0; mq < 8; mq++) {
            *(ulonglong2*)(Pn + mq * 64 + j * 8)     = make_ulonglong2(acc[mq][0], acc[mq][1]);
            *(ulonglong2*)(Pn + mq * 64 + j * 8 + 4) = make_ulonglong2(acc[mq][2], acc[mq][3]);
        }
    }
}

// ---------------- fused prep: blocks [0,2048) scatter edges; [2048,3072) node prep layer 0 ----------------
__global__ void __launch_bounds__(256)
k_prep(const int* __restrict__ src, const int* __restrict__ dst,
       const float* __restrict__ rel_pos, const int* __restrict__ species,
       const float* __restrict__ Wq, const float* __restrict__ W3,
       const float* __restrict__ b3, const float* __restrict__ W1n,
       const float* __restrict__ b1n) {
    __shared__ float sW3p[8 * W3P_STRIDE];
    __shared__ float sW1[CC * MIDD];
    __shared__ float sWq[HH * CC];
    __shared__ float sb3[256];
    __shared__ float sb1[MIDD];
    __shared__ float sXn[32 * CC];
    __shared__ float sSn[32 * CC];
    int tid = threadIdx.x;

    if (blockIdx.x < 2048) {
        int e = blockIdx.x * 256 + tid;
        int s = src[e], d = dst[e];
        float px = rel_pos[e * 3 + 0], py = rel_pos[e * 3 + 1], pz = rel_pos[e * 3 + 2];
        float dist = sqrtf(px * px + py * py + pz * pz);
        float xc = dist / CUTOFFF;
        bool in_cut = dist < CUTOFFF;
        float x2 = in_cut ? fminf(xc * xc, 1.f - 1e-6f) : 0.f;
        float scale = in_cut ? expf(3.f - 3.f / (1.f - x2)) : 0.f;

        int ps = atomicAdd(&g_cursrc[s], 1);
        int pd = atomicAdd(&g_curdst[d], 1);
        g_srcS[ps] = s;
        g_eidxD[pd] = ps;
        g_distS[ps] = dist;
        g_scaleS[ps] = scale;
        g_scaleD[pd] = scale;

        float Zu = (float)species[s];
        float Zv = (float)species[d];
        float raw = KCOULF * Zu * Zv / (2.f * dist);
        float au = 0.8854f * 0.529f / (__powf(Zu, 0.23f) + __powf(Zv, 0.23f));
        float xx = dist / au;
        float screen = 0.1818f * __expf(-3.2f * xx) + 0.5099f * __expf(-0.9423f * xx)
                     + 0.2802f * __expf(-0.4028f * xx) + 0.02817f * __expf(-0.2016f * xx);
        g_contribD[pd] = raw * screen * scale;
        return;
    }

    int blk = blockIdx.x - 2048;
    load_node_weights(tid, W3, b3, W1n, b1n, Wq, nullptr,
                      sW3p, sW1, sWq, sb3, sb1, nullptr);
    int nloc = tid >> 3, j = tid & 7;
    int n = blk * 32 + nloc;
    sXn[nloc * CC + j] = g_x[n * CC + j];
    sXn[nloc * CC + 8 + j] = g_x[n * CC + 8 + j];
    sSn[nloc * CC + j] = 0.f;
    sSn[nloc * CC + 8 + j] = 0.f;
    __syncthreads();
    node_prep(n, nloc, j, true, false, sW3p, sW1, sWq, sb3, sb1, nullptr, sXn, sSn);
}

// ---------------- node layer: attention (gathered) + Wproj + prep next weights ----------------
__global__ void __launch_bounds__(256)
k_node_layer(int mode,
             const float* __restrict__ Wproj,
             const float* __restrict__ Wq,
             const float* __restrict__ W3,
             const float* __restrict__ b3,
             const float* __restrict__ W1n,
             const float* __restrict__ b1n,
             const float* __restrict__ Wself) {
    __shared__ float sW3p[8 * W3P_STRIDE];
    __shared__ float sW1[CC * MIDD];
    __shared__ float sWq[HH * CC];
    __shared__ float sWproj[CC * 24];
    __shared__ float sb3[256];
    __shared__ float sb1[MIDD];
    __shared__ float sWself[CC * CC];
    __shared__ float sAgg[32 * HH];
    __shared__ float sXold[32 * CC];
    __shared__ float sXn[32 * CC];
    __shared__ float sSn[32 * CC];

    int tid = threadIdx.x;
    int nloc = tid >> 3, j = tid & 7;
    int n = blockIdx.x * 32 + nloc;

    load_node_weights(tid, W3, b3, W1n, b1n,
                      mode != 2 ? Wq : nullptr,
                      mode == 2 ? Wself : nullptr,
                      sW3p, sW1, sWq, sb3, sb1, sWself);
    for (int idx = tid; idx < CC * 24; idx += 256) sWproj[idx] = Wproj[idx];

    {
        int beg = g_rdst[n], end = g_rdst[n + 1];
        float qj = g_q[n * HH + j];   // this layer's q (written by previous prep)
        float mx = -INFINITY;
        for (int i = beg; i < end; i++) {
            int ei = g_eidxD[i];
            float2 vk = *(const float2*)(g_vk + (size_t)ei * CC + j * 2);
            mx = fmaxf(mx, vk.y * qj);
        }
        float num = 0.f, den = 0.f;
        for (int i = beg; i < end; i++) {
            int ei = g_eidxD[i];
            float2 vk = *(const float2*)(g_vk + (size_t)ei * CC + j * 2);
            float w = g_scaleD[i] * __expf(vk.y * qj - mx);
            den += w;
            num = fmaf(w, vk.x, num);
        }
        sAgg[nloc * HH + j] = num / fmaxf(den, 1e-20f);
        sXold[nloc * CC + j] = g_x[n * CC + j];
        sXold[nloc * CC + 8 + j] = g_x[n * CC + 8 + j];
        __syncthreads();
        float xn0 = 0.f, xn1 = 0.f;
#pragma unroll
        for (int k = 0; k < 8; k++) {
            float a = sAgg[nloc * HH + k];
            xn0 = fmaf(sWproj[j * 24 + k], a, xn0);
            xn1 = fmaf(sWproj[(j + 8) * 24 + k], a, xn1);
        }
#pragma unroll
        for (int k = 0; k < CC; k++) {
            float xo = sXold[nloc * CC + k];
            xn0 = fmaf(sWproj[j * 24 + 8 + k], xo, xn0);
            xn1 = fmaf(sWproj[(j + 8) * 24 + 8 + k], xo, xn1);
        }
        float s0 = g_S[n * CC + j] + xn0;
        float s1 = g_S[n * CC + 8 + j] + xn1;
        g_x[n * CC + j] = xn0;     g_x[n * CC + 8 + j] = xn1;
        g_S[n * CC + j] = s0;      g_S[n * CC + 8 + j] = s1;
        sXn[nloc * CC + j] = xn0;  sXn[nloc * CC + 8 + j] = xn1;
        sSn[nloc * CC + j] = s0;   sSn[nloc * CC + 8 + j] = s1;
        __syncthreads();
    }

    node_prep(n, nloc, j, mode != 2, mode == 2,
              sW3p, sW1, sWq, sb3, sb1, sWself, sXn, sSn);
}

// ---------------- edge kernel: thread-per-edge, fully coalesced I/O ----------------
__global__ void __launch_bounds__(256)
k_edge(const float* __restrict__ W1, const float* __restrict__ W2,
       const float* __restrict__ b2) {
    __shared__ ull sW2p[512];   // [i2][jp]
    __shared__ float sw15[MIDD];
    __shared__ ull sB2p[16];
    int tid = threadIdx.x;
    for (int i = tid; i < 512; i += 256) sW2p[i] = ((const ull*)W2)[i];
    if (tid < MIDD) sw15[tid] = W1[15 * MIDD + tid];
    if (tid < 16) sB2p[tid] = ((const ull*)b2)[tid];
    __syncthreads();

    int e = blockIdx.x * 256 + tid;
    int s = g_srcS[e];
    float dist = g_distS[e];
    float bs = Y0F * g_scaleS[e];

    // radial MLP (u-trick): h1 = relu(u[s] + dist*w15); h2 = relu(W2^T h1 + b2)
    float h2[MIDD];
    {
        float h1[MIDD];
        const float4* up = (const float4*)(g_u + (size_t)s * MIDD);
#pragma unroll
        for (int t = 0; t < 8; t++) {
            float4 uv = up[t];
            h1[4 * t + 0] = fmaxf(fmaf(dist, sw15[4 * t + 0], uv.x), 0.f);
            h1[4 * t + 1] = fmaxf(fmaf(dist, sw15[4 * t + 1], uv.y), 0.f);
            h1[4 * t + 2] = fmaxf(fmaf(dist, sw15[4 * t + 2], uv.z), 0.f);
            h1[4 * t + 3] = fmaxf(fmaf(dist, sw15[4 * t + 3], uv.w), 0.f);
        }
        ull acc[16];
#pragma unroll
        for (int jp = 0; jp < 16; jp++) acc[jp] = sB2p[jp];
#pragma unroll
        for (int i2 = 0; i2 < MIDD; i2++) {
            ull xx = pack2(h1[i2], h1[i2]);
#pragma unroll
            for (int jp = 0; jp < 16; jp++)
                acc[jp] = fma2(xx, sW2p[i2 * 16 + jp], acc[jp]);
        }
#pragma unroll
        for (int jp = 0; jp < 16; jp++) {
            float lo, hi;
            unpack2(acc[jp], lo, hi);
            h2[2 * jp] = fmaxf(lo, 0.f);
            h2[2 * jp + 1] = fmaxf(hi, 0.f);
        }
    }

    // contraction: kacc[j] = (val[j], key[j]) — P lines dedup across warp (sorted src)
    ull kacc[8];
    {
        const ulonglong2* pbp = (const ulonglong2*)(g_PB + (size_t)s * CC);
#pragma unroll
        for (int t = 0; t < 4; t++) {
            ulonglong2 pb = pbp[t];
            kacc[2 * t] = pb.x;
            kacc[2 * t + 1] = pb.y;
        }
        const ull* Pp = (const ull*)(g_P + (size_t)s * 512);
#pragma unroll
        for (int mq = 0; mq < 8; mq++) {
            ull x0 = pack2(h2[mq * 4 + 0], h2[mq * 4 + 0]);
            ull x1 = pack2(h2[mq * 4 + 1], h2[mq * 4 + 1]);
            ull x2 = pack2(h2[mq * 4 + 2], h2[mq * 4 + 2]);
            ull x3 = pack2(h2[mq * 4 + 3], h2[mq * 4 + 3]);
#pragma unroll
            for (int j = 0; j < 8; j++) {
                ulonglong2 pA = *(const ulonglong2*)(Pp + mq * 32 + j * 4);
                ulonglong2 pB = *(const ulonglong2*)(Pp + mq * 32 + j * 4 + 2);
                kacc[j] = fma2(x0, pA.x, kacc[j]);
                kacc[j] = fma2(x1, pA.y, kacc[j]);
                kacc[j] = fma2(x2, pB.x, kacc[j]);
                kacc[j] = fma2(x3, pB.y, kacc[j]);
            }
        }
    }

    // coalesced store at src-sorted position e
    float4 ov[4];
#pragma unroll
    for (int t = 0; t < 4; t++) {
        float a0, b0, a1, b1;
        unpack2(kacc[2 * t], a0, b0);
        unpack2(kacc[2 * t + 1], a1, b1);
        ov[t] = make_float4(a0 * bs, b0 * bs, a1 * bs, b1 * bs);
    }
    float4* dp = (float4*)(g_vk + (size_t)e * CC);
    dp[0] = ov[0]; dp[1] = ov[1]; dp[2] = ov[2]; dp[3] = ov[3];
}

// ---------------- final: gather msg + coulomb + per-atom MLP + reduce ----------------
__device__ __forceinline__ float siluf(float x) { return x / (1.f + __expf(-x)); }

__global__ void k_final(const int* __restrict__ species, const float* __restrict__ emb,
                        const float* __restrict__ W1, const float* __restrict__ b1,
                        const float* __restrict__ W2, const float* __restrict__ b2,
                        const float* __restrict__ W3, const float* __restrict__ b3,
                        float* __restrict__ out) {
    __shared__ float sFeat[16 * 17];
    __shared__ float sEmb[16 * 17];
    __shared__ float sH[16 * 17];
    __shared__ float sCoul[16];
    __shared__ float sRed[16];
    int tid = threadIdx.x;
    int nloc = tid >> 4, o = tid & 15;
    int n = blockIdx.x * 16 + nloc;
    int beg = g_rdst[n], end = g_rdst[n + 1];
    int o2 = (o < 8) ? o * 2 : (o - 8) * 2 + 1;   // pair-interleaved layout
    float f = g_feats[n * CC + o];
    for (int i = beg; i < end; i++) {
        int ei = g_eidxD[i];
        f += g_vk[(size_t)ei * CC + o2];
    }
    sFeat[nloc * 17 + o] = f;
    if (o == 0) {
        float c = 0.f;
        for (int i = beg; i < end; i++) c += g_contribD[i];
        sCoul[nloc] = c;
    }
    int sp = species[n] - 1;
    sEmb[nloc * 17 + o] = emb[sp * CC + o];
    __syncthreads();

    float h1 = b1[o];
#pragma unroll
    for (int k = 0; k < CC; k++) h1 = fmaf(sEmb[nloc * 17 + k], W1[k * CC + o], h1);
#pragma unroll
    for (int k = 0; k < CC; k++) h1 = fmaf(sFeat[nloc * 17 + k], W1[(CC + k) * CC + o], h1);
    sH[nloc * 17 + o] = siluf(h1);
    __syncthreads();

    float h2 = b2[o];
#pragma unroll
    for (int k = 0; k < CC; k++) h2 = fmaf(sH[nloc * 17 + k], W2[k * CC + o], h2);
    h2 = siluf(h2);

    float part = h2 * W3[o];
#pragma unroll
    for (int off = 8; off > 0; off >>= 1)
        part += __shfl_down_sync(0xffffffffu, part, off, 16);
    if (o == 0) sRed[nloc] = part + b3[0] + sCoul[nloc];
    __syncthreads();
    if (tid == 0) {
        float acc = 0.f;
#pragma unroll
        for (int k = 0; k < 16; k++) acc += sRed[k];
        atomicAdd(out, acc);
    }
}

// ---------------- host launch ----------------
extern "C" void kernel_launch(void* const* d_in, const int* in_sizes, int n_in,
                              void* d_out, int out_size) {
    const int* species  = (const int*)d_in[0];
    const int* src      = (const int*)d_in[1];
    const int* dst      = (const int*)d_in[2];
    const float* rel_pos = (const float*)d_in[3];
    const float* emb    = (const float*)d_in[4];
    const float* kv_W1  = (const float*)d_in[5];
    const float* kv_b1  = (const float*)d_in[6];
    const float* kv_W2  = (const float*)d_in[7];
    const float* kv_b2  = (const float*)d_in[8];
    const float* kv_W3  = (const float*)d_in[9];
    const float* kv_b3  = (const float*)d_in[10];
    const float* Wq     = (const float*)d_in[11];
    const float* Wproj  = (const float*)d_in[12];
    const float* fin_W1 = (const float*)d_in[13];
    const float* fin_b1 = (const float*)d_in[14];
    const float* fin_W2 = (const float*)d_in[15];
    const float* fin_b2 = (const float*)d_in[16];
    const float* fin_W3 = (const float*)d_in[17];
    const float* fin_b3 = (const float*)d_in[18];
    const float* Wself  = (const float*)d_in[19];
    const float* mlp_W1 = (const float*)d_in[20];
    const float* mlp_b1 = (const float*)d_in[21];
    const float* mlp_W2 = (const float*)d_in[22];
    const float* mlp_b2 = (const float*)d_in[23];
    const float* mlp_W3 = (const float*)d_in[24];
    const float* mlp_b3 = (const float*)d_in[25];
    float* out = (float*)d_out;

    const int EB = EE / 256;   // 2048
    const int LB = NN / 32;    // 1024

    k_init<<<EB, 256>>>(species, emb, out, src, dst);
    k_scan<<<2, 1024>>>();
    k_prep<<<EB + LB, 256>>>(src, dst, rel_pos, species,
                             Wq, kv_W3, kv_b3, kv_W1, kv_b1);

    for (int l = 0; l < 4; l++) {
        k_edge<<<EB, 256>>>(kv_W1 + (size_t)l * CC * MIDD,
                            kv_W2 + (size_t)l * MIDD * MIDD,
                            kv_b2 + (size_t)l * MIDD);
        if (l < 3) {
            k_node_layer<<<LB, 256>>>(1,
                Wproj + (size_t)l * CC * 24,
                Wq + (size_t)(l + 1) * HH * CC,
                kv_W3 + (size_t)(l + 1) * MIDD * 256,
                kv_b3 + (size_t)(l + 1) * 256,
                kv_W1 + (size_t)(l + 1) * CC * MIDD,
                kv_b1 + (size_t)(l + 1) * MIDD,
                nullptr);
        } else {
            k_node_layer<<<LB, 256>>>(2,
                Wproj + (size_t)l * CC * 24,
                nullptr,
                fin_W3, fin_b3, fin_W1, fin_b1, Wself);
        }
    }
    k_edge<<<EB, 256>>>(fin_W1, fin_W2, fin_b2);
    k_final<<<NN / 16, 256>>>(species, emb, mlp_W1, mlp_b1, mlp_W2, mlp_b2,
                              mlp_W3, mlp_b3, out);
}

// round 7
// speedup vs baseline: 1.1640x; 1.0386x over previous
#include <cuda_runtime.h>
#include <math.h>

#define NN 32768
#define EE 524288
#define EENP (EE + NN)          // padded src-sorted capacity (557056 = 256*2176)
#define CC 16
#define MIDD 32
#define HH 8
#define Y0F 0.28209479177387814f
#define CUTOFFF 4.6f
#define KCOULF 0.529f

typedef unsigned long long ull;

// ---------------- device scratch ----------------
__device__ __align__(16) float g_x[NN * CC];
__device__ __align__(16) float g_S[NN * CC];
__device__ __align__(16) float g_q[NN * HH];
__device__ __align__(16) float g_u[NN * MIDD];
__device__ __align__(16) float g_P[NN * 512];     // pair-interleaved
__device__ __align__(16) float g_PB[NN * CC];     // pair-interleaved
__device__ __align__(16) float g_feats[NN * CC];
__device__ __align__(16) float g_vk[(size_t)EENP * CC]; // padded src-sorted {val,key} pairs
__device__ float g_distS[EENP];
__device__ float g_scaleS[EENP];
__device__ float g_scaleD[EE];
__device__ float g_contribD[EE];
__device__ int g_srcS[EENP];
__device__ int g_eidxD[EE];                       // dst-order -> padded src-order index
__device__ int g_csrc[NN], g_cdst[NN];
__device__ int g_rdst[NN + 1];
__device__ int g_cursrc[NN], g_curdst[NN];

// ---------------- f32x2 helpers ----------------
__device__ __forceinline__ ull pack2(float a, float b) {
    ull r;
    asm("mov.b64 %0, {%1, %2};" : "=l"(r) : "f"(a), "f"(b));
    return r;
}
__device__ __forceinline__ ull fma2(ull a, ull b, ull c) {
    ull d;
    asm("fma.rn.f32x2 %0, %1, %2, %3;" : "=l"(d) : "l"(a), "l"(b), "l"(c));
    return d;
}
__device__ __forceinline__ void unpack2(ull v, float& lo, float& hi) {
    asm("mov.b64 {%0, %1}, %2;" : "=f"(lo), "=f"(hi) : "l"(v));
}

// ---------------- init: node init + edge histogram (counters zeroed by prior k_scan) ----------------
__global__ void k_init(const int* __restrict__ species, const float* __restrict__ emb,
                       float* __restrict__ out,
                       const int* __restrict__ src, const int* __restrict__ dst) {
    int e = blockIdx.x * 256 + threadIdx.x;
    if (e < NN) {
        int sp = species[e] - 1;
#pragma unroll
        for (int c = 0; c < CC; c++) {
            g_x[e * CC + c] = emb[sp * CC + c];
            g_S[e * CC + c] = 0.f;
        }
        if (e == 0) out[0] = 0.f;
    }
    atomicAdd(&g_csrc[src[e]], 1);
    atomicAdd(&g_cdst[dst[e]], 1);
}

// ---------------- scan: src side PADDED to even per-node counts; writes dummy-slot srcS ----------------
__global__ void k_scan() {
    const int T = 1024, PER = NN / 1024;
    __shared__ int part[T];
    int t = threadIdx.x;
    int base = t * PER;
    if (blockIdx.x == 0) {
        // src side, padded
        int loc[PER], locp[PER];
        int s = 0;
#pragma unroll
        for (int i = 0; i < PER; i++) {
            loc[i] = g_csrc[base + i];
            g_csrc[base + i] = 0;
            locp[i] = (loc[i] + 1) & ~1;
            s += locp[i];
        }
        part[t] = s;
        __syncthreads();
        for (int off = 1; off < T; off <<= 1) {
            int v = (t >= off) ? part[t - off] : 0;
            __syncthreads();
            part[t] += v;
            __syncthreads();
        }
        int run = part[t] - s;
#pragma unroll
        for (int i = 0; i < PER; i++) {
            g_cursrc[base + i] = run;
            if (loc[i] & 1) g_srcS[run + loc[i]] = base + i;  // dummy slot same-src
            run += locp[i];
        }
    } else {
        // dst side, unpadded
        int loc[PER];
        int s = 0;
#pragma unroll
        for (int i = 0; i < PER; i++) {
            loc[i] = g_cdst[base + i];
            g_cdst[base + i] = 0;
            s += loc[i];
        }
        part[t] = s;
        __syncthreads();
        for (int off = 1; off < T; off <<= 1) {
            int v = (t >= off) ? part[t - off] : 0;
            __syncthreads();
            part[t] += v;
            __syncthreads();
        }
        int run = part[t] - s;
#pragma unroll
        for (int i = 0; i < PER; i++) {
            g_rdst[base + i] = run;
            g_curdst[base + i] = run;
            run += loc[i];
        }
        if (t == T - 1) g_rdst[NN] = run;
    }
}

// ---------------- shared node-prep helpers ----------------
#define W3P_STRIDE 1036

__device__ __forceinline__ void load_node_weights(
    int tid, const float* __restrict__ W3, const float* __restrict__ b3,
    const float* __restrict__ W1n, const float* __restrict__ b1n,
    const float* __restrict__ Wq, const float* __restrict__ Wself,
    float* sW3p, float* sW1, float* sWq, float* sb3, float* sb1, float* sWself) {
    for (int idx = tid; idx < MIDD * 256; idx += 256) {
        int m = idx >> 8, k = idx & 255;
        int o = k >> 4, i = k & 15;
        sW3p[(o & 7) * W3P_STRIDE + i * 64 + m * 2 + (o >> 3)] = W3[idx];
    }
    for (int idx = tid; idx < CC * MIDD; idx += 256) sW1[idx] = W1n[idx];
    if (Wq && tid < HH * CC) sWq[tid] = Wq[tid];
    sb3[tid] = b3[tid];
    if (tid < MIDD) sb1[tid] = b1n[tid];
    if (Wself && tid < CC * CC) sWself[tid] = Wself[tid];
}

__device__ __forceinline__ void node_prep(
    int n, int nloc, int j, bool do_q, bool do_feats,
    const float* sW3p, const float* sW1, const float* sWq,
    const float* sb3, const float* sb1, const float* sWself,
    const float* sXn, const float* sSn) {
    if (do_q) {
        float qa = 0.f;
#pragma unroll
        for (int c = 0; c < CC; c++) qa = fmaf(sWq[j * CC + c], sXn[nloc * CC + c], qa);
        g_q[n * HH + j] = qa;
    }
    {
        float u0 = sb1[j], u1 = sb1[j + 8], u2 = sb1[j + 16], u3 = sb1[j + 24];
#pragma unroll
        for (int c = 0; c < CC; c++) {
            float sv = sSn[nloc * CC + c];
            u0 = fmaf(sv, sW1[c * MIDD + j], u0);
            u1 = fmaf(sv, sW1[c * MIDD + j + 8], u1);
            u2 = fmaf(sv, sW1[c * MIDD + j + 16], u2);
            u3 = fmaf(sv, sW1[c * MIDD + j + 24], u3);
        }
        g_u[n * MIDD + j] = u0;
        g_u[n * MIDD + j + 8] = u1;
        g_u[n * MIDD + j + 16] = u2;
        g_u[n * MIDD + j + 24] = u3;
    }
    {
        float pb0 = 0.f, pb1 = 0.f;
#pragma unroll
        for (int i = 0; i < CC; i++) {
            float xv = sXn[nloc * CC + i];
            pb0 = fmaf(sb3[j * CC + i], xv, pb0);
            pb1 = fmaf(sb3[(j + 8) * CC + i], xv, pb1);
        }
        g_PB[n * CC + j * 2] = pb0;
        g_PB[n * CC + j * 2 + 1] = pb1;
    }
    if (do_feats) {
        float f0 = 0.f, f1 = 0.f;
#pragma unroll
        for (int i = 0; i < CC; i++) {
            float xv = sXn[nloc * CC + i];
            f0 = fmaf(sWself[j * CC + i], xv, f0);
            f1 = fmaf(sWself[(j + 8) * CC + i], xv, f1);
        }
        g_feats[n * CC + j] = f0;
        g_feats[n * CC + 8 + j] = f1;
    }
    {
        ull acc[8][4];
#pragma unroll
        for (int mq = 0; mq < 8; mq++)
#pragma unroll
            for (int r = 0; r < 4; r++) acc[mq][r] = 0ULL;
#pragma unroll
        for (int i = 0; i < CC; i++) {
            float xv = sXn[nloc * CC + i];
            ull xx = pack2(xv, xv);
            const ull* wp = (const ull*)&sW3p[j * W3P_STRIDE + i * 64];
#pragma unroll
            for (int mq = 0; mq < 8; mq++) {
                acc[mq][0] = fma2(xx, wp[mq * 4 + 0], acc[mq][0]);
                acc[mq][1] = fma2(xx, wp[mq * 4 + 1], acc[mq][1]);
                acc[mq][2] = fma2(xx, wp[mq * 4 + 2], acc[mq][2]);
                acc[mq][3] = fma2(xx, wp[mq * 4 + 3], acc[mq][3]);
            }
        }
        float* Pn = g_P + (size_t)n * 512;
#pragma unroll
        for (int mq = 0; mq < 8; mq++) {
            *(ulonglong2*)(Pn + mq * 64 + j * 8)     = make_ulonglong2(acc[mq][0], acc[mq][1]);
            *(ulonglong2*)(Pn + mq * 64 + j * 8 + 4) = make_ulonglong2(acc[mq][2], acc[mq][3]);
        }
    }
}

// ---------------- fused prep: blocks [0,2048) scatter edges; [2048,3072) node prep layer 0 ----------------
__global__ void __launch_bounds__(256)
k_prep(const int* __restrict__ src, const int* __restrict__ dst,
       const float* __restrict__ rel_pos, const int* __restrict__ species,
       const float* __restrict__ Wq, const float* __restrict__ W3,
       const float* __restrict__ b3, const float* __restrict__ W1n,
       const float* __restrict__ b1n) {
    __shared__ float sW3p[8 * W3P_STRIDE];
    __shared__ float sW1[CC * MIDD];
    __shared__ float sWq[HH * CC];
    __shared__ float sb3[256];
    __shared__ float sb1[MIDD];
    __shared__ float sXn[32 * CC];
    __shared__ float sSn[32 * CC];
    int tid = threadIdx.x;

    if (blockIdx.x < 2048) {
        int e = blockIdx.x * 256 + tid;
        int s = src[e], d = dst[e];
        float px = rel_pos[e * 3 + 0], py = rel_pos[e * 3 + 1], pz = rel_pos[e * 3 + 2];
        float dist = sqrtf(px * px + py * py + pz * pz);
        float xc = dist / CUTOFFF;
        bool in_cut = dist < CUTOFFF;
        float x2 = in_cut ? fminf(xc * xc, 1.f - 1e-6f) : 0.f;
        float scale = in_cut ? expf(3.f - 3.f / (1.f - x2)) : 0.f;

        int ps = atomicAdd(&g_cursrc[s], 1);
        int pd = atomicAdd(&g_curdst[d], 1);
        g_srcS[ps] = s;
        g_eidxD[pd] = ps;
        g_distS[ps] = dist;
        g_scaleS[ps] = scale;
        g_scaleD[pd] = scale;

        float Zu = (float)species[s];
        float Zv = (float)species[d];
        float raw = KCOULF * Zu * Zv / (2.f * dist);
        float au = 0.8854f * 0.529f / (__powf(Zu, 0.23f) + __powf(Zv, 0.23f));
        float xx = dist / au;
        float screen = 0.1818f * __expf(-3.2f * xx) + 0.5099f * __expf(-0.9423f * xx)
                     + 0.2802f * __expf(-0.4028f * xx) + 0.02817f * __expf(-0.2016f * xx);
        g_contribD[pd] = raw * screen * scale;
        return;
    }

    int blk = blockIdx.x - 2048;
    load_node_weights(tid, W3, b3, W1n, b1n, Wq, nullptr,
                      sW3p, sW1, sWq, sb3, sb1, nullptr);
    int nloc = tid >> 3, j = tid & 7;
    int n = blk * 32 + nloc;
    sXn[nloc * CC + j] = g_x[n * CC + j];
    sXn[nloc * CC + 8 + j] = g_x[n * CC + 8 + j];
    sSn[nloc * CC + j] = 0.f;
    sSn[nloc * CC + 8 + j] = 0.f;
    __syncthreads();
    node_prep(n, nloc, j, true, false, sW3p, sW1, sWq, sb3, sb1, nullptr, sXn, sSn);
}

// ---------------- node layer: attention (gathered) + Wproj + prep next weights ----------------
__global__ void __launch_bounds__(256)
k_node_layer(int mode,
             const float* __restrict__ Wproj,
             const float* __restrict__ Wq,
             const float* __restrict__ W3,
             const float* __restrict__ b3,
             const float* __restrict__ W1n,
             const float* __restrict__ b1n,
             const float* __restrict__ Wself) {
    __shared__ float sW3p[8 * W3P_STRIDE];
    __shared__ float sW1[CC * MIDD];
    __shared__ float sWq[HH * CC];
    __shared__ float sWproj[CC * 24];
    __shared__ float sb3[256];
    __shared__ float sb1[MIDD];
    __shared__ float sWself[CC * CC];
    __shared__ float sAgg[32 * HH];
    __shared__ float sXold[32 * CC];
    __shared__ float sXn[32 * CC];
    __shared__ float sSn[32 * CC];

    int tid = threadIdx.x;
    int nloc = tid >> 3, j = tid & 7;
    int n = blockIdx.x * 32 + nloc;

    load_node_weights(tid, W3, b3, W1n, b1n,
                      mode != 2 ? Wq : nullptr,
                      mode == 2 ? Wself : nullptr,
                      sW3p, sW1, sWq, sb3, sb1, sWself);
    for (int idx = tid; idx < CC * 24; idx += 256) sWproj[idx] = Wproj[idx];

    {
        int beg = g_rdst[n], end = g_rdst[n + 1];
        float qj = g_q[n * HH + j];
        float mx = -INFINITY;
        for (int i = beg; i < end; i++) {
            int ei = g_eidxD[i];
            float2 vk = *(const float2*)(g_vk + (size_t)ei * CC + j * 2);
            mx = fmaxf(mx, vk.y * qj);
        }
        float num = 0.f, den = 0.f;
        for (int i = beg; i < end; i++) {
            int ei = g_eidxD[i];
            float2 vk = *(const float2*)(g_vk + (size_t)ei * CC + j * 2);
            float w = g_scaleD[i] * __expf(vk.y * qj - mx);
            den += w;
            num = fmaf(w, vk.x, num);
        }
        sAgg[nloc * HH + j] = num / fmaxf(den, 1e-20f);
        sXold[nloc * CC + j] = g_x[n * CC + j];
        sXold[nloc * CC + 8 + j] = g_x[n * CC + 8 + j];
        __syncthreads();
        float xn0 = 0.f, xn1 = 0.f;
#pragma unroll
        for (int k = 0; k < 8; k++) {
            float a = sAgg[nloc * HH + k];
            xn0 = fmaf(sWproj[j * 24 + k], a, xn0);
            xn1 = fmaf(sWproj[(j + 8) * 24 + k], a, xn1);
        }
#pragma unroll
        for (int k = 0; k < CC; k++) {
            float xo = sXold[nloc * CC + k];
            xn0 = fmaf(sWproj[j * 24 + 8 + k], xo, xn0);
            xn1 = fmaf(sWproj[(j + 8) * 24 + 8 + k], xo, xn1);
        }
        float s0 = g_S[n * CC + j] + xn0;
        float s1 = g_S[n * CC + 8 + j] + xn1;
        g_x[n * CC + j] = xn0;     g_x[n * CC + 8 + j] = xn1;
        g_S[n * CC + j] = s0;      g_S[n * CC + 8 + j] = s1;
        sXn[nloc * CC + j] = xn0;  sXn[nloc * CC + 8 + j] = xn1;
        sSn[nloc * CC + j] = s0;   sSn[nloc * CC + 8 + j] = s1;
        __syncthreads();
    }

    node_prep(n, nloc, j, mode != 2, mode == 2,
              sW3p, sW1, sWq, sb3, sb1, sWself, sXn, sSn);
}

// ---------------- edge kernel: 2 same-src edges per thread, shared u/PB/P/W2 operands ----------------
__global__ void __launch_bounds__(128)
k_edge(const float* __restrict__ W1, const float* __restrict__ W2,
       const float* __restrict__ b2) {
    __shared__ __align__(16) ull sW2p[512];   // [i2][jp]
    __shared__ float sw15[MIDD];
    __shared__ __align__(16) ull sB2p[16];
    int tid = threadIdx.x;
    for (int i = tid; i < 512; i += 128) sW2p[i] = ((const ull*)W2)[i];
    if (tid < MIDD) sw15[tid] = W1[15 * MIDD + tid];
    if (tid < 16) sB2p[tid] = ((const ull*)b2)[tid];
    __syncthreads();

    int t = blockIdx.x * 128 + tid;
    int e0 = 2 * t;                       // pair (e0, e0+1) share src by construction
    int s = g_srcS[e0];
    float2 dd = *(const float2*)(g_distS + e0);
    float2 sc = *(const float2*)(g_scaleS + e0);
    float da = dd.x, db = dd.y;
    float bsa = Y0F * sc.x, bsb = Y0F * sc.y;

    // u (shared by both edges) into registers
    float u[MIDD];
    {
        const float4* up = (const float4*)(g_u + (size_t)s * MIDD);
#pragma unroll
        for (int k = 0; k < 8; k++) {
            float4 v = up[k];
            u[4 * k] = v.x; u[4 * k + 1] = v.y; u[4 * k + 2] = v.z; u[4 * k + 3] = v.w;
        }
    }

    // W2 matvec for both edges; h1 computed inline (never stored)
    ull acca[16], accb[16];
#pragma unroll
    for (int jp = 0; jp < 16; jp++) { acca[jp] = sB2p[jp]; accb[jp] = sB2p[jp]; }
#pragma unroll
    for (int i2 = 0; i2 < MIDD; i2++) {
        float w15v = sw15[i2];
        float ha = fmaxf(fmaf(da, w15v, u[i2]), 0.f);
        float hb = fmaxf(fmaf(db, w15v, u[i2]), 0.f);
        ull xa = pack2(ha, ha);
        ull xb = pack2(hb, hb);
#pragma unroll
        for (int jq = 0; jq < 8; jq++) {
            ulonglong2 w = *(const ulonglong2*)&sW2p[i2 * 16 + jq * 2];
            acca[2 * jq]     = fma2(xa, w.x, acca[2 * jq]);
            acca[2 * jq + 1] = fma2(xa, w.y, acca[2 * jq + 1]);
            accb[2 * jq]     = fma2(xb, w.x, accb[2 * jq]);
            accb[2 * jq + 1] = fma2(xb, w.y, accb[2 * jq + 1]);
        }
    }
    float h2a[MIDD], h2b[MIDD];
#pragma unroll
    for (int jp = 0; jp < 16; jp++) {
        float lo, hi;
        unpack2(acca[jp], lo, hi);
        h2a[2 * jp] = fmaxf(lo, 0.f); h2a[2 * jp + 1] = fmaxf(hi, 0.f);
        unpack2(accb[jp], lo, hi);
        h2b[2 * jp] = fmaxf(lo, 0.f); h2b[2 * jp + 1] = fmaxf(hi, 0.f);
    }

    // contraction for both edges; P/PB loaded once
    ull ka[8], kb[8];
    {
        const ulonglong2* pbp = (const ulonglong2*)(g_PB + (size_t)s * CC);
#pragma unroll
        for (int q = 0; q < 4; q++) {
            ulonglong2 pb = pbp[q];
            ka[2 * q] = pb.x; ka[2 * q + 1] = pb.y;
            kb[2 * q] = pb.x; kb[2 * q + 1] = pb.y;
        }
    }
    const ull* Pp = (const ull*)(g_P + (size_t)s * 512);
#pragma unroll
    for (int mq = 0; mq < 8; mq++) {
        ull xa0 = pack2(h2a[mq * 4 + 0], h2a[mq * 4 + 0]);
        ull xa1 = pack2(h2a[mq * 4 + 1], h2a[mq * 4 + 1]);
        ull xa2 = pack2(h2a[mq * 4 + 2], h2a[mq * 4 + 2]);
        ull xa3 = pack2(h2a[mq * 4 + 3], h2a[mq * 4 + 3]);
        ull xb0 = pack2(h2b[mq * 4 + 0], h2b[mq * 4 + 0]);
        ull xb1 = pack2(h2b[mq * 4 + 1], h2b[mq * 4 + 1]);
        ull xb2 = pack2(h2b[mq * 4 + 2], h2b[mq * 4 + 2]);
        ull xb3 = pack2(h2b[mq * 4 + 3], h2b[mq * 4 + 3]);
#pragma unroll
        for (int j = 0; j < 8; j++) {
            ulonglong2 pA = *(const ulonglong2*)(Pp + mq * 32 + j * 4);
            ulonglong2 pB = *(const ulonglong2*)(Pp + mq * 32 + j * 4 + 2);
            ka[j] = fma2(xa0, pA.x, ka[j]);
            ka[j] = fma2(xa1, pA.y, ka[j]);
            ka[j] = fma2(xa2, pB.x, ka[j]);
            ka[j] = fma2(xa3, pB.y, ka[j]);
            kb[j] = fma2(xb0, pA.x, kb[j]);
            kb[j] = fma2(xb1, pA.y, kb[j]);
            kb[j] = fma2(xb2, pB.x, kb[j]);
            kb[j] = fma2(xb3, pB.y, kb[j]);
        }
    }

    // coalesced stores: 128B contiguous per thread
    float4* dp = (float4*)(g_vk + (size_t)e0 * CC);
#pragma unroll
    for (int q = 0; q < 4; q++) {
        float a0, a1, a2, a3;
        unpack2(ka[2 * q], a0, a1);
        unpack2(ka[2 * q + 1], a2, a3);
        dp[q] = make_float4(a0 * bsa, a1 * bsa, a2 * bsa, a3 * bsa);
    }
#pragma unroll
    for (int q = 0; q < 4; q++) {
        float a0, a1, a2, a3;
        unpack2(kb[2 * q], a0, a1);
        unpack2(kb[2 * q + 1], a2, a3);
        dp[4 + q] = make_float4(a0 * bsb, a1 * bsb, a2 * bsb, a3 * bsb);
    }
}

// ---------------- final: gather msg + coulomb + per-atom MLP + reduce ----------------
__device__ __forceinline__ float siluf(float x) { return x / (1.f + __expf(-x)); }

__global__ void k_final(const int* __restrict__ species, const float* __restrict__ emb,
                        const float* __restrict__ W1, const float* __restrict__ b1,
                        const float* __restrict__ W2, const float* __restrict__ b2,
                        const float* __restrict__ W3, const float* __restrict__ b3,
                        float* __restrict__ out) {
    __shared__ float sFeat[16 * 17];
    __shared__ float sEmb[16 * 17];
    __shared__ float sH[16 * 17];
    __shared__ float sCoul[16];
    __shared__ float sRed[16];
    int tid = threadIdx.x;
    int nloc = tid >> 4, o = tid & 15;
    int n = blockIdx.x * 16 + nloc;
    int beg = g_rdst[n], end = g_rdst[n + 1];
    int o2 = (o < 8) ? o * 2 : (o - 8) * 2 + 1;
    float f = g_feats[n * CC + o];
    for (int i = beg; i < end; i++) {
        int ei = g_eidxD[i];
        f += g_vk[(size_t)ei * CC + o2];
    }
    sFeat[nloc * 17 + o] = f;
    if (o == 0) {
        float c = 0.f;
        for (int i = beg; i < end; i++) c += g_contribD[i];
        sCoul[nloc] = c;
    }
    int sp = species[n] - 1;
    sEmb[nloc * 17 + o] = emb[sp * CC + o];
    __syncthreads();

    float h1 = b1[o];
#pragma unroll
    for (int k = 0; k < CC; k++) h1 = fmaf(sEmb[nloc * 17 + k], W1[k * CC + o], h1);
#pragma unroll
    for (int k = 0; k < CC; k++) h1 = fmaf(sFeat[nloc * 17 + k], W1[(CC + k) * CC + o], h1);
    sH[nloc * 17 + o] = siluf(h1);
    __syncthreads();

    float h2 = b2[o];
#pragma unroll
    for (int k = 0; k < CC; k++) h2 = fmaf(sH[nloc * 17 + k], W2[k * CC + o], h2);
    h2 = siluf(h2);

    float part = h2 * W3[o];
#pragma unroll
    for (int off = 8; off > 0; off >>= 1)
        part += __shfl_down_sync(0xffffffffu, part, off, 16);
    if (o == 0) sRed[nloc] = part + b3[0] + sCoul[nloc];
    __syncthreads();
    if (tid == 0) {
        float acc = 0.f;
#pragma unroll
        for (int k = 0; k < 16; k++) acc += sRed[k];
        atomicAdd(out, acc);
    }
}

// ---------------- host launch ----------------
extern "C" void kernel_launch(void* const* d_in, const int* in_sizes, int n_in,
                              void* d_out, int out_size) {
    const int* species  = (const int*)d_in[0];
    const int* src      = (const int*)d_in[1];
    const int* dst      = (const int*)d_in[2];
    const float* rel_pos = (const float*)d_in[3];
    const float* emb    = (const float*)d_in[4];
    const float* kv_W1  = (const float*)d_in[5];
    const float* kv_b1  = (const float*)d_in[6];
    const float* kv_W2  = (const float*)d_in[7];
    const float* kv_b2  = (const float*)d_in[8];
    const float* kv_W3  = (const float*)d_in[9];
    const float* kv_b3  = (const float*)d_in[10];
    const float* Wq     = (const float*)d_in[11];
    const float* Wproj  = (const float*)d_in[12];
    const float* fin_W1 = (const float*)d_in[13];
    const float* fin_b1 = (const float*)d_in[14];
    const float* fin_W2 = (const float*)d_in[15];
    const float* fin_b2 = (const float*)d_in[16];
    const float* fin_W3 = (const float*)d_in[17];
    const float* fin_b3 = (const float*)d_in[18];
    const float* Wself  = (const float*)d_in[19];
    const float* mlp_W1 = (const float*)d_in[20];
    const float* mlp_b1 = (const float*)d_in[21];
    const float* mlp_W2 = (const float*)d_in[22];
    const float* mlp_b2 = (const float*)d_in[23];
    const float* mlp_W3 = (const float*)d_in[24];
    const float* mlp_b3 = (const float*)d_in[25];
    float* out = (float*)d_out;

    const int EB = EE / 256;         // 2048
    const int LB = NN / 32;          // 1024
    const int EDGB = EENP / 256;     // 2176 (128 threads x 2 edges)

    k_init<<<EB, 256>>>(species, emb, out, src, dst);
    k_scan<<<2, 1024>>>();
    k_prep<<<EB + LB, 256>>>(src, dst, rel_pos, species,
                             Wq, kv_W3, kv_b3, kv_W1, kv_b1);

    for (int l = 0; l < 4; l++) {
        k_edge<<<EDGB, 128>>>(kv_W1 + (size_t)l * CC * MIDD,
                              kv_W2 + (size_t)l * MIDD * MIDD,
                              kv_b2 + (size_t)l * MIDD);
        if (l < 3) {
            k_node_layer<<<LB, 256>>>(1,
                Wproj + (size_t)l * CC * 24,
                Wq + (size_t)(l + 1) * HH * CC,
                kv_W3 + (size_t)(l + 1) * MIDD * 256,
                kv_b3 + (size_t)(l + 1) * 256,
                kv_W1 + (size_t)(l + 1) * CC * MIDD,
                kv_b1 + (size_t)(l + 1) * MIDD,
                nullptr);
        } else {
            k_node_layer<<<LB, 256>>>(2,
                Wproj + (size_t)l * CC * 24,
                nullptr,
                fin_W3, fin_b3, fin_W1, fin_b1, Wself);
        }
    }
    k_edge<<<EDGB, 128>>>(fin_W1, fin_W2, fin_b2);
    k_final<<<NN / 16, 256>>>(species, emb, mlp_W1, mlp_b1, mlp_W2, mlp_b2,
                              mlp_W3, mlp_b3, out);
}

// round 8
// speedup vs baseline: 1.3291x; 1.1419x over previous
#include <cuda_runtime.h>
#include <math.h>

#define NN 32768
#define EE 524288
#define EENP (EE + NN)          // padded src-sorted capacity (557056 = 256*2176)
#define CC 16
#define MIDD 32
#define HH 8
#define Y0F 0.28209479177387814f
#define CUTOFFF 4.6f
#define KCOULF 0.529f

typedef unsigned long long ull;

// ---------------- device scratch ----------------
__device__ __align__(16) float g_x[NN * CC];
__device__ __align__(16) float g_S[NN * CC];
__device__ __align__(16) float g_q[NN * HH];
__device__ __align__(16) float g_u[NN * MIDD];
__device__ __align__(16) float g_P[NN * 512];     // pair-interleaved
__device__ __align__(16) float g_PB[NN * CC];     // pair-interleaved
__device__ __align__(16) float g_feats[NN * CC];
__device__ __align__(16) float g_vk[(size_t)EENP * CC]; // padded src-sorted {val,key} pairs
__device__ float g_distS[EENP];
__device__ float g_scaleS[EENP];
__device__ float g_scaleD[EE];
__device__ float g_contribD[EE];
__device__ int g_srcS[EENP];
__device__ int g_eidxD[EE];                       // dst-order -> padded src-order index
__device__ int g_csrc[NN], g_cdst[NN];
__device__ int g_rdst[NN + 1];
__device__ int g_cursrc[NN], g_curdst[NN];

// ---------------- f32x2 helpers ----------------
__device__ __forceinline__ ull pack2(float a, float b) {
    ull r;
    asm("mov.b64 %0, {%1, %2};" : "=l"(r) : "f"(a), "f"(b));
    return r;
}
__device__ __forceinline__ ull fma2(ull a, ull b, ull c) {
    ull d;
    asm("fma.rn.f32x2 %0, %1, %2, %3;" : "=l"(d) : "l"(a), "l"(b), "l"(c));
    return d;
}
__device__ __forceinline__ void unpack2(ull v, float& lo, float& hi) {
    asm("mov.b64 {%0, %1}, %2;" : "=f"(lo), "=f"(hi) : "l"(v));
}

// ---------------- init ----------------
__global__ void k_init(const int* __restrict__ species, const float* __restrict__ emb,
                       float* __restrict__ out,
                       const int* __restrict__ src, const int* __restrict__ dst) {
    int e = blockIdx.x * 256 + threadIdx.x;
    if (e < NN) {
        int sp = species[e] - 1;
#pragma unroll
        for (int c = 0; c < CC; c++) {
            g_x[e * CC + c] = emb[sp * CC + c];
            g_S[e * CC + c] = 0.f;
        }
        if (e == 0) out[0] = 0.f;
    }
    atomicAdd(&g_csrc[src[e]], 1);
    atomicAdd(&g_cdst[dst[e]], 1);
}

// ---------------- scan: src side padded to even; counters reset ----------------
__global__ void k_scan() {
    const int T = 1024, PER = NN / 1024;
    __shared__ int part[T];
    int t = threadIdx.x;
    int base = t * PER;
    if (blockIdx.x == 0) {
        int loc[PER], locp[PER];
        int s = 0;
#pragma unroll
        for (int i = 0; i < PER; i++) {
            loc[i] = g_csrc[base + i];
            g_csrc[base + i] = 0;
            locp[i] = (loc[i] + 1) & ~1;
            s += locp[i];
        }
        part[t] = s;
        __syncthreads();
        for (int off = 1; off < T; off <<= 1) {
            int v = (t >= off) ? part[t - off] : 0;
            __syncthreads();
            part[t] += v;
            __syncthreads();
        }
        int run = part[t] - s;
#pragma unroll
        for (int i = 0; i < PER; i++) {
            g_cursrc[base + i] = run;
            if (loc[i] & 1) g_srcS[run + loc[i]] = base + i;
            run += locp[i];
        }
    } else {
        int loc[PER];
        int s = 0;
#pragma unroll
        for (int i = 0; i < PER; i++) {
            loc[i] = g_cdst[base + i];
            g_cdst[base + i] = 0;
            s += loc[i];
        }
        part[t] = s;
        __syncthreads();
        for (int off = 1; off < T; off <<= 1) {
            int v = (t >= off) ? part[t - off] : 0;
            __syncthreads();
            part[t] += v;
            __syncthreads();
        }
        int run = part[t] - s;
#pragma unroll
        for (int i = 0; i < PER; i++) {
            g_rdst[base + i] = run;
            g_curdst[base + i] = run;
            run += loc[i];
        }
        if (t == T - 1) g_rdst[NN] = run;
    }
}

// ---------------- shared node-prep helpers ----------------
#define W3P_STRIDE 1036

__device__ __forceinline__ void load_node_weights(
    int tid, const float* __restrict__ W3, const float* __restrict__ b3,
    const float* __restrict__ W1n, const float* __restrict__ b1n,
    const float* __restrict__ Wq, const float* __restrict__ Wself,
    float* sW3p, float* sW1, float* sWq, float* sb3, float* sb1, float* sWself) {
    for (int idx = tid; idx < MIDD * 256; idx += 256) {
        int m = idx >> 8, k = idx & 255;
        int o = k >> 4, i = k & 15;
        sW3p[(o & 7) * W3P_STRIDE + i * 64 + m * 2 + (o >> 3)] = W3[idx];
    }
    for (int idx = tid; idx < CC * MIDD; idx += 256) sW1[idx] = W1n[idx];
    if (Wq && tid < HH * CC) sWq[tid] = Wq[tid];
    sb3[tid] = b3[tid];
    if (tid < MIDD) sb1[tid] = b1n[tid];
    if (Wself && tid < CC * CC) sWself[tid] = Wself[tid];
}

__device__ __forceinline__ void node_prep(
    int n, int nloc, int j, bool do_q, bool do_feats,
    const float* sW3p, const float* sW1, const float* sWq,
    const float* sb3, const float* sb1, const float* sWself,
    const float* sXn, const float* sSn) {
    if (do_q) {
        float qa = 0.f;
#pragma unroll
        for (int c = 0; c < CC; c++) qa = fmaf(sWq[j * CC + c], sXn[nloc * CC + c], qa);
        g_q[n * HH + j] = qa;
    }
    {
        float u0 = sb1[j], u1 = sb1[j + 8], u2 = sb1[j + 16], u3 = sb1[j + 24];
#pragma unroll
        for (int c = 0; c < CC; c++) {
            float sv = sSn[nloc * CC + c];
            u0 = fmaf(sv, sW1[c * MIDD + j], u0);
            u1 = fmaf(sv, sW1[c * MIDD + j + 8], u1);
            u2 = fmaf(sv, sW1[c * MIDD + j + 16], u2);
            u3 = fmaf(sv, sW1[c * MIDD + j + 24], u3);
        }
        g_u[n * MIDD + j] = u0;
        g_u[n * MIDD + j + 8] = u1;
        g_u[n * MIDD + j + 16] = u2;
        g_u[n * MIDD + j + 24] = u3;
    }
    {
        float pb0 = 0.f, pb1 = 0.f;
#pragma unroll
        for (int i = 0; i < CC; i++) {
            float xv = sXn[nloc * CC + i];
            pb0 = fmaf(sb3[j * CC + i], xv, pb0);
            pb1 = fmaf(sb3[(j + 8) * CC + i], xv, pb1);
        }
        g_PB[n * CC + j * 2] = pb0;
        g_PB[n * CC + j * 2 + 1] = pb1;
    }
    if (do_feats) {
        float f0 = 0.f, f1 = 0.f;
#pragma unroll
        for (int i = 0; i < CC; i++) {
            float xv = sXn[nloc * CC + i];
            f0 = fmaf(sWself[j * CC + i], xv, f0);
            f1 = fmaf(sWself[(j + 8) * CC + i], xv, f1);
        }
        g_feats[n * CC + j] = f0;
        g_feats[n * CC + 8 + j] = f1;
    }
    {
        ull acc[8][4];
#pragma unroll
        for (int mq = 0; mq < 8; mq++)
#pragma unroll
            for (int r = 0; r < 4; r++) acc[mq][r] = 0ULL;
#pragma unroll
        for (int i = 0; i < CC; i++) {
            float xv = sXn[nloc * CC + i];
            ull xx = pack2(xv, xv);
            const ull* wp = (const ull*)&sW3p[j * W3P_STRIDE + i * 64];
#pragma unroll
            for (int mq = 0; mq < 8; mq++) {
                acc[mq][0] = fma2(xx, wp[mq * 4 + 0], acc[mq][0]);
                acc[mq][1] = fma2(xx, wp[mq * 4 + 1], acc[mq][1]);
                acc[mq][2] = fma2(xx, wp[mq * 4 + 2], acc[mq][2]);
                acc[mq][3] = fma2(xx, wp[mq * 4 + 3], acc[mq][3]);
            }
        }
        float* Pn = g_P + (size_t)n * 512;
#pragma unroll
        for (int mq = 0; mq < 8; mq++) {
            *(ulonglong2*)(Pn + mq * 64 + j * 8)     = make_ulonglong2(acc[mq][0], acc[mq][1]);
            *(ulonglong2*)(Pn + mq * 64 + j * 8 + 4) = make_ulonglong2(acc[mq][2], acc[mq][3]);
        }
    }
}

// ---------------- fused prep: blocks [0,2048) scatter; [2048,3072) node prep layer 0 ----------------
__global__ void __launch_bounds__(256)
k_prep(const int* __restrict__ src, const int* __restrict__ dst,
       const float* __restrict__ rel_pos, const int* __restrict__ species,
       const float* __restrict__ Wq, const float* __restrict__ W3,
       const float* __restrict__ b3, const float* __restrict__ W1n,
       const float* __restrict__ b1n) {
    __shared__ float sW3p[8 * W3P_STRIDE];
    __shared__ float sW1[CC * MIDD];
    __shared__ float sWq[HH * CC];
    __shared__ float sb3[256];
    __shared__ float sb1[MIDD];
    __shared__ float sXn[32 * CC];
    __shared__ float sSn[32 * CC];
    int tid = threadIdx.x;

    if (blockIdx.x < 2048) {
        int e = blockIdx.x * 256 + tid;
        int s = src[e], d = dst[e];
        float px = rel_pos[e * 3 + 0], py = rel_pos[e * 3 + 1], pz = rel_pos[e * 3 + 2];
        float dist = sqrtf(px * px + py * py + pz * pz);
        float xc = dist / CUTOFFF;
        bool in_cut = dist < CUTOFFF;
        float x2 = in_cut ? fminf(xc * xc, 1.f - 1e-6f) : 0.f;
        float scale = in_cut ? expf(3.f - 3.f / (1.f - x2)) : 0.f;

        int ps = atomicAdd(&g_cursrc[s], 1);
        int pd = atomicAdd(&g_curdst[d], 1);
        g_srcS[ps] = s;
        g_eidxD[pd] = ps;
        g_distS[ps] = dist;
        g_scaleS[ps] = scale;
        g_scaleD[pd] = scale;

        float Zu = (float)species[s];
        float Zv = (float)species[d];
        float raw = KCOULF * Zu * Zv / (2.f * dist);
        float au = 0.8854f * 0.529f / (__powf(Zu, 0.23f) + __powf(Zv, 0.23f));
        float xx = dist / au;
        float screen = 0.1818f * __expf(-3.2f * xx) + 0.5099f * __expf(-0.9423f * xx)
                     + 0.2802f * __expf(-0.4028f * xx) + 0.02817f * __expf(-0.2016f * xx);
        g_contribD[pd] = raw * screen * scale;
        return;
    }

    int blk = blockIdx.x - 2048;
    load_node_weights(tid, W3, b3, W1n, b1n, Wq, nullptr,
                      sW3p, sW1, sWq, sb3, sb1, nullptr);
    int nloc = tid >> 3, j = tid & 7;
    int n = blk * 32 + nloc;
    sXn[nloc * CC + j] = g_x[n * CC + j];
    sXn[nloc * CC + 8 + j] = g_x[n * CC + 8 + j];
    sSn[nloc * CC + j] = 0.f;
    sSn[nloc * CC + 8 + j] = 0.f;
    __syncthreads();
    node_prep(n, nloc, j, true, false, sW3p, sW1, sWq, sb3, sb1, nullptr, sXn, sSn);
}

// ---------------- node layer: ONE-PASS online-softmax attention + Wproj + prep ----------------
__global__ void __launch_bounds__(256)
k_node_layer(int mode,
             const float* __restrict__ Wproj,
             const float* __restrict__ Wq,
             const float* __restrict__ W3,
             const float* __restrict__ b3,
             const float* __restrict__ W1n,
             const float* __restrict__ b1n,
             const float* __restrict__ Wself) {
    __shared__ float sW3p[8 * W3P_STRIDE];
    __shared__ float sW1[CC * MIDD];
    __shared__ float sWq[HH * CC];
    __shared__ float sWproj[CC * 24];
    __shared__ float sb3[256];
    __shared__ float sb1[MIDD];
    __shared__ float sWself[CC * CC];
    __shared__ float sAgg[32 * HH];
    __shared__ float sXold[32 * CC];
    __shared__ float sXn[32 * CC];
    __shared__ float sSn[32 * CC];

    int tid = threadIdx.x;
    int nloc = tid >> 3, j = tid & 7;
    int n = blockIdx.x * 32 + nloc;

    load_node_weights(tid, W3, b3, W1n, b1n,
                      mode != 2 ? Wq : nullptr,
                      mode == 2 ? Wself : nullptr,
                      sW3p, sW1, sWq, sb3, sb1, sWself);
    for (int idx = tid; idx < CC * 24; idx += 256) sWproj[idx] = Wproj[idx];

    {
        int beg = g_rdst[n], end = g_rdst[n + 1];
        float qj = g_q[n * HH + j];
        float m = -INFINITY, num = 0.f, den = 0.f;
        for (int i = beg; i < end; i++) {
            int ei = g_eidxD[i];
            float2 vk = *(const float2*)(g_vk + (size_t)ei * CC + j * 2);
            float sc = g_scaleD[i];
            float l = vk.y * qj;
            float mn = fmaxf(m, l);
            float corr = __expf(m - mn);          // 0 on first iteration
            float p = sc * __expf(l - mn);
            den = den * corr + p;
            num = fmaf(num, corr, p * vk.x);
            m = mn;
        }
        sAgg[nloc * HH + j] = num / fmaxf(den, 1e-20f);
        sXold[nloc * CC + j] = g_x[n * CC + j];
        sXold[nloc * CC + 8 + j] = g_x[n * CC + 8 + j];
        __syncthreads();
        float xn0 = 0.f, xn1 = 0.f;
#pragma unroll
        for (int k = 0; k < 8; k++) {
            float a = sAgg[nloc * HH + k];
            xn0 = fmaf(sWproj[j * 24 + k], a, xn0);
            xn1 = fmaf(sWproj[(j + 8) * 24 + k], a, xn1);
        }
#pragma unroll
        for (int k = 0; k < CC; k++) {
            float xo = sXold[nloc * CC + k];
            xn0 = fmaf(sWproj[j * 24 + 8 + k], xo, xn0);
            xn1 = fmaf(sWproj[(j + 8) * 24 + 8 + k], xo, xn1);
        }
        float s0 = g_S[n * CC + j] + xn0;
        float s1 = g_S[n * CC + 8 + j] + xn1;
        g_x[n * CC + j] = xn0;     g_x[n * CC + 8 + j] = xn1;
        g_S[n * CC + j] = s0;      g_S[n * CC + 8 + j] = s1;
        sXn[nloc * CC + j] = xn0;  sXn[nloc * CC + 8 + j] = xn1;
        sSn[nloc * CC + j] = s0;   sSn[nloc * CC + 8 + j] = s1;
        __syncthreads();
    }

    node_prep(n, nloc, j, mode != 2, mode == 2,
              sW3p, sW1, sWq, sb3, sb1, sWself, sXn, sSn);
}

// ---------------- edge kernel: 2 same-src edges/thread, smem-staged coalesced stores ----------------
__global__ void __launch_bounds__(128, 4)
k_edge(const float* __restrict__ W1, const float* __restrict__ W2,
       const float* __restrict__ b2) {
    __shared__ __align__(16) ull sW2p[512];   // [i2][jp]
    __shared__ float sw15[MIDD];
    __shared__ __align__(16) ull sB2p[16];
    __shared__ __align__(16) float sSt[4][32 * 36];   // per-warp staging (36-float stride)
    int tid = threadIdx.x;
    for (int i = tid; i < 512; i += 128) sW2p[i] = ((const ull*)W2)[i];
    if (tid < MIDD) sw15[tid] = W1[15 * MIDD + tid];
    if (tid < 16) sB2p[tid] = ((const ull*)b2)[tid];
    __syncthreads();

    int t = blockIdx.x * 128 + tid;
    int e0 = 2 * t;                       // pair (e0, e0+1) share src by construction
    int s = g_srcS[e0];
    float2 dd = *(const float2*)(g_distS + e0);
    float2 sc = *(const float2*)(g_scaleS + e0);
    float da = dd.x, db = dd.y;
    float bsa = Y0F * sc.x, bsb = Y0F * sc.y;

    // u (shared by both edges)
    float u[MIDD];
    {
        const float4* up = (const float4*)(g_u + (size_t)s * MIDD);
#pragma unroll
        for (int k = 0; k < 8; k++) {
            float4 v = up[k];
            u[4 * k] = v.x; u[4 * k + 1] = v.y; u[4 * k + 2] = v.z; u[4 * k + 3] = v.w;
        }
    }

    // W2 matvec for both edges; h1 inline
    ull acca[16], accb[16];
#pragma unroll
    for (int jp = 0; jp < 16; jp++) { acca[jp] = sB2p[jp]; accb[jp] = sB2p[jp]; }
#pragma unroll
    for (int i2 = 0; i2 < MIDD; i2++) {
        float w15v = sw15[i2];
        float ha = fmaxf(fmaf(da, w15v, u[i2]), 0.f);
        float hb = fmaxf(fmaf(db, w15v, u[i2]), 0.f);
        ull xa = pack2(ha, ha);
        ull xb = pack2(hb, hb);
#pragma unroll
        for (int jq = 0; jq < 8; jq++) {
            ulonglong2 w = *(const ulonglong2*)&sW2p[i2 * 16 + jq * 2];
            acca[2 * jq]     = fma2(xa, w.x, acca[2 * jq]);
            acca[2 * jq + 1] = fma2(xa, w.y, acca[2 * jq + 1]);
            accb[2 * jq]     = fma2(xb, w.x, accb[2 * jq]);
            accb[2 * jq + 1] = fma2(xb, w.y, accb[2 * jq + 1]);
        }
    }
    float h2a[MIDD], h2b[MIDD];
#pragma unroll
    for (int jp = 0; jp < 16; jp++) {
        float lo, hi;
        unpack2(acca[jp], lo, hi);
        h2a[2 * jp] = fmaxf(lo, 0.f); h2a[2 * jp + 1] = fmaxf(hi, 0.f);
        unpack2(accb[jp], lo, hi);
        h2b[2 * jp] = fmaxf(lo, 0.f); h2b[2 * jp + 1] = fmaxf(hi, 0.f);
    }

    // contraction for both edges; P/PB loaded once
    ull ka[8], kb[8];
    {
        const ulonglong2* pbp = (const ulonglong2*)(g_PB + (size_t)s * CC);
#pragma unroll
        for (int q = 0; q < 4; q++) {
            ulonglong2 pb = pbp[q];
            ka[2 * q] = pb.x; ka[2 * q + 1] = pb.y;
            kb[2 * q] = pb.x; kb[2 * q + 1] = pb.y;
        }
    }
    const ull* Pp = (const ull*)(g_P + (size_t)s * 512);
#pragma unroll
    for (int mq = 0; mq < 8; mq++) {
        ull xa0 = pack2(h2a[mq * 4 + 0], h2a[mq * 4 + 0]);
        ull xa1 = pack2(h2a[mq * 4 + 1], h2a[mq * 4 + 1]);
        ull xa2 = pack2(h2a[mq * 4 + 2], h2a[mq * 4 + 2]);
        ull xa3 = pack2(h2a[mq * 4 + 3], h2a[mq * 4 + 3]);
        ull xb0 = pack2(h2b[mq * 4 + 0], h2b[mq * 4 + 0]);
        ull xb1 = pack2(h2b[mq * 4 + 1], h2b[mq * 4 + 1]);
        ull xb2 = pack2(h2b[mq * 4 + 2], h2b[mq * 4 + 2]);
        ull xb3 = pack2(h2b[mq * 4 + 3], h2b[mq * 4 + 3]);
#pragma unroll
        for (int j = 0; j < 8; j++) {
            ulonglong2 pA = *(const ulonglong2*)(Pp + mq * 32 + j * 4);
            ulonglong2 pB = *(const ulonglong2*)(Pp + mq * 32 + j * 4 + 2);
            ka[j] = fma2(xa0, pA.x, ka[j]);
            ka[j] = fma2(xa1, pA.y, ka[j]);
            ka[j] = fma2(xa2, pB.x, ka[j]);
            ka[j] = fma2(xa3, pB.y, ka[j]);
            kb[j] = fma2(xb0, pA.x, kb[j]);
            kb[j] = fma2(xb1, pA.y, kb[j]);
            kb[j] = fma2(xb2, pB.x, kb[j]);
            kb[j] = fma2(xb3, pB.y, kb[j]);
        }
    }

    // stage 32 floats (2 edges x 16) into smem, then warp-coalesced STG
    int lane = tid & 31, w = tid >> 5;
    float* st = sSt[w];
#pragma unroll
    for (int q = 0; q < 4; q++) {
        float a0, a1, a2, a3;
        unpack2(ka[2 * q], a0, a1);
        unpack2(ka[2 * q + 1], a2, a3);
        *(float4*)&st[lane * 36 + q * 4] = make_float4(a0 * bsa, a1 * bsa, a2 * bsa, a3 * bsa);
    }
#pragma unroll
    for (int q = 0; q < 4; q++) {
        float a0, a1, a2, a3;
        unpack2(kb[2 * q], a0, a1);
        unpack2(kb[2 * q + 1], a2, a3);
        *(float4*)&st[lane * 36 + 16 + q * 4] = make_float4(a0 * bsb, a1 * bsb, a2 * bsb, a3 * bsb);
    }
    __syncwarp();
    // warp covers edges [blockIdx*256 + w*64, +64) -> 256 contiguous float4s
    float4* gbase = (float4*)(g_vk + (size_t)(blockIdx.x * 256 + w * 64) * CC);
#pragma unroll
    for (int g = 0; g < 8; g++) {
        int f = g * 32 + lane;
        int owner = f >> 3, q = f & 7;
        gbase[f] = *(const float4*)&st[owner * 36 + q * 4];
    }
}

// ---------------- final ----------------
__device__ __forceinline__ float siluf(float x) { return x / (1.f + __expf(-x)); }

__global__ void k_final(const int* __restrict__ species, const float* __restrict__ emb,
                        const float* __restrict__ W1, const float* __restrict__ b1,
                        const float* __restrict__ W2, const float* __restrict__ b2,
                        const float* __restrict__ W3, const float* __restrict__ b3,
                        float* __restrict__ out) {
    __shared__ float sFeat[16 * 17];
    __shared__ float sEmb[16 * 17];
    __shared__ float sH[16 * 17];
    __shared__ float sCoul[16];
    __shared__ float sRed[16];
    int tid = threadIdx.x;
    int nloc = tid >> 4, o = tid & 15;
    int n = blockIdx.x * 16 + nloc;
    int beg = g_rdst[n], end = g_rdst[n + 1];
    int o2 = (o < 8) ? o * 2 : (o - 8) * 2 + 1;
    float f = g_feats[n * CC + o];
    for (int i = beg; i < end; i++) {
        int ei = g_eidxD[i];
        f += g_vk[(size_t)ei * CC + o2];
    }
    sFeat[nloc * 17 + o] = f;
    if (o == 0) {
        float c = 0.f;
        for (int i = beg; i < end; i++) c += g_contribD[i];
        sCoul[nloc] = c;
    }
    int sp = species[n] - 1;
    sEmb[nloc * 17 + o] = emb[sp * CC + o];
    __syncthreads();

    float h1 = b1[o];
#pragma unroll
    for (int k = 0; k < CC; k++) h1 = fmaf(sEmb[nloc * 17 + k], W1[k * CC + o], h1);
#pragma unroll
    for (int k = 0; k < CC; k++) h1 = fmaf(sFeat[nloc * 17 + k], W1[(CC + k) * CC + o], h1);
    sH[nloc * 17 + o] = siluf(h1);
    __syncthreads();

    float h2 = b2[o];
#pragma unroll
    for (int k = 0; k < CC; k++) h2 = fmaf(sH[nloc * 17 + k], W2[k * CC + o], h2);
    h2 = siluf(h2);

    float part = h2 * W3[o];
#pragma unroll
    for (int off = 8; off > 0; off >>= 1)
        part += __shfl_down_sync(0xffffffffu, part, off, 16);
    if (o == 0) sRed[nloc] = part + b3[0] + sCoul[nloc];
    __syncthreads();
    if (tid == 0) {
        float acc = 0.f;
#pragma unroll
        for (int k = 0; k < 16; k++) acc += sRed[k];
        atomicAdd(out, acc);
    }
}

// ---------------- host launch ----------------
extern "C" void kernel_launch(void* const* d_in, const int* in_sizes, int n_in,
                              void* d_out, int out_size) {
    const int* species  = (const int*)d_in[0];
    const int* src      = (const int*)d_in[1];
    const int* dst      = (const int*)d_in[2];
    const float* rel_pos = (const float*)d_in[3];
    const float* emb    = (const float*)d_in[4];
    const float* kv_W1  = (const float*)d_in[5];
    const float* kv_b1  = (const float*)d_in[6];
    const float* kv_W2  = (const float*)d_in[7];
    const float* kv_b2  = (const float*)d_in[8];
    const float* kv_W3  = (const float*)d_in[9];
    const float* kv_b3  = (const float*)d_in[10];
    const float* Wq     = (const float*)d_in[11];
    const float* Wproj  = (const float*)d_in[12];
    const float* fin_W1 = (const float*)d_in[13];
    const float* fin_b1 = (const float*)d_in[14];
    const float* fin_W2 = (const float*)d_in[15];
    const float* fin_b2 = (const float*)d_in[16];
    const float* fin_W3 = (const float*)d_in[17];
    const float* fin_b3 = (const float*)d_in[18];
    const float* Wself  = (const float*)d_in[19];
    const float* mlp_W1 = (const float*)d_in[20];
    const float* mlp_b1 = (const float*)d_in[21];
    const float* mlp_W2 = (const float*)d_in[22];
    const float* mlp_b2 = (const float*)d_in[23];
    const float* mlp_W3 = (const float*)d_in[24];
    const float* mlp_b3 = (const float*)d_in[25];
    float* out = (float*)d_out;

    const int EB = EE / 256;         // 2048
    const int LB = NN / 32;          // 1024
    const int EDGB = EENP / 256;     // 2176

    k_init<<<EB, 256>>>(species, emb, out, src, dst);
    k_scan<<<2, 1024>>>();
    k_prep<<<EB + LB, 256>>>(src, dst, rel_pos, species,
                             Wq, kv_W3, kv_b3, kv_W1, kv_b1);

    for (int l = 0; l < 4; l++) {
        k_edge<<<EDGB, 128>>>(kv_W1 + (size_t)l * CC * MIDD,
                              kv_W2 + (size_t)l * MIDD * MIDD,
                              kv_b2 + (size_t)l * MIDD);
        if (l < 3) {
            k_node_layer<<<LB, 256>>>(1,
                Wproj + (size_t)l * CC * 24,
                Wq + (size_t)(l + 1) * HH * CC,
                kv_W3 + (size_t)(l + 1) * MIDD * 256,
                kv_b3 + (size_t)(l + 1) * 256,
                kv_W1 + (size_t)(l + 1) * CC * MIDD,
                kv_b1 + (size_t)(l + 1) * MIDD,
                nullptr);
        } else {
            k_node_layer<<<LB, 256>>>(2,
                Wproj + (size_t)l * CC * 24,
                nullptr,
                fin_W3, fin_b3, fin_W1, fin_b1, Wself);
        }
    }
    k_edge<<<EDGB, 128>>>(fin_W1, fin_W2, fin_b2);
    k_final<<<NN / 16, 256>>>(species, emb, mlp_W1, mlp_b1, mlp_W2, mlp_b2,
                              mlp_W3, mlp_b3, out);
}